// round 1
// baseline (speedup 1.0000x reference)
#include <cuda_runtime.h>
#include <cuda_bf16.h>
#include <math.h>

// Problem constants
#define BB 2
#define TT 1024
#define DMODEL 3072
#define NHEADS 32
#define NKV 8
#define HD 96
#define NTOK (BB*TT)          // 2048
#define QDIM (NHEADS*HD)      // 3072
#define KVDIM (NKV*HD)        // 768

// Scratch (static device globals; no allocation allowed)
__device__ float g_q[NTOK*QDIM];
__device__ float g_k[NTOK*KVDIM];
__device__ float g_v[NTOK*KVDIM];
__device__ float g_attn[NTOK*QDIM];

// ---------------------------------------------------------------------------
// SGEMM: C[M,N] = A[M,K] * B[N,K]^T   (both A and B are K-major row-major)
// 128x128 block tile, 16x16 threads, 8x8 per thread, K-tile 16.
// Assumes M%128==0, N%128==0, K%16==0 (true for all calls here).
// ---------------------------------------------------------------------------
#define GT 128
#define KT 16
__global__ __launch_bounds__(256, 2)
void sgemm_nt_kernel(const float* __restrict__ A, const float* __restrict__ B,
                     float* __restrict__ C, int M, int N, int K)
{
    __shared__ float As[KT][GT];
    __shared__ float Bs[KT][GT];

    const int tx = threadIdx.x & 15;
    const int ty = threadIdx.x >> 4;
    const int m0 = blockIdx.y * GT;
    const int n0 = blockIdx.x * GT;

    float acc[8][8];
#pragma unroll
    for (int i = 0; i < 8; i++)
#pragma unroll
        for (int j = 0; j < 8; j++) acc[i][j] = 0.f;

    for (int k0 = 0; k0 < K; k0 += KT) {
        // Load A tile (128 rows x 16 k) and B tile, transposed into smem.
        // 512 float4 each; 256 threads -> 2 per thread per tile.
#pragma unroll
        for (int l = threadIdx.x; l < (GT * KT) / 4; l += 256) {
            int row = l >> 2;
            int kc  = (l & 3) * 4;
            float4 va = *(const float4*)&A[(size_t)(m0 + row) * K + k0 + kc];
            As[kc + 0][row] = va.x; As[kc + 1][row] = va.y;
            As[kc + 2][row] = va.z; As[kc + 3][row] = va.w;
            float4 vb = *(const float4*)&B[(size_t)(n0 + row) * K + k0 + kc];
            Bs[kc + 0][row] = vb.x; Bs[kc + 1][row] = vb.y;
            Bs[kc + 2][row] = vb.z; Bs[kc + 3][row] = vb.w;
        }
        __syncthreads();

#pragma unroll
        for (int kk = 0; kk < KT; kk++) {
            float a[8], b[8];
            float4 a0 = *(float4*)&As[kk][ty * 8];
            float4 a1 = *(float4*)&As[kk][ty * 8 + 4];
            a[0]=a0.x; a[1]=a0.y; a[2]=a0.z; a[3]=a0.w;
            a[4]=a1.x; a[5]=a1.y; a[6]=a1.z; a[7]=a1.w;
            float4 b0 = *(float4*)&Bs[kk][tx * 8];
            float4 b1 = *(float4*)&Bs[kk][tx * 8 + 4];
            b[0]=b0.x; b[1]=b0.y; b[2]=b0.z; b[3]=b0.w;
            b[4]=b1.x; b[5]=b1.y; b[6]=b1.z; b[7]=b1.w;
#pragma unroll
            for (int i = 0; i < 8; i++)
#pragma unroll
                for (int j = 0; j < 8; j++)
                    acc[i][j] += a[i] * b[j];
        }
        __syncthreads();
    }

#pragma unroll
    for (int i = 0; i < 8; i++) {
        float* crow = &C[(size_t)(m0 + ty * 8 + i) * N + n0 + tx * 8];
#pragma unroll
        for (int j = 0; j < 8; j += 4) {
            float4 v = make_float4(acc[i][j], acc[i][j+1], acc[i][j+2], acc[i][j+3]);
            *(float4*)&crow[j] = v;
        }
    }
}

// ---------------------------------------------------------------------------
// Fused RMSNorm + RoPE (in place). One warp per (token, head).
// Matches reference exactly:
//   out[2i]   = xn[2i]*cos[2i]   - xn[2i+1]*sin[2i]
//   out[2i+1] = xn[2i]*sin[2i+1] + xn[2i+1]*cos[2i+1]
// ---------------------------------------------------------------------------
__global__ void norm_rope_kernel(float* __restrict__ buf,
                                 const float* __restrict__ w,
                                 const float* __restrict__ cosb,
                                 const float* __restrict__ sinb,
                                 int H, int total_rows)
{
    int gw = (blockIdx.x * blockDim.x + threadIdx.x) >> 5;
    if (gw >= total_rows) return;
    int lane = threadIdx.x & 31;
    int h   = gw % H;
    int tok = gw / H;
    int tpos = tok & (TT - 1);
    float* row = buf + (size_t)tok * H * HD + (size_t)h * HD;

    float2 v0 = *(float2*)&row[2 * lane];
    float2 v1 = make_float2(0.f, 0.f);
    if (lane < 16) v1 = *(float2*)&row[2 * (lane + 32)];

    float ss = v0.x*v0.x + v0.y*v0.y + v1.x*v1.x + v1.y*v1.y;
#pragma unroll
    for (int off = 16; off; off >>= 1)
        ss += __shfl_xor_sync(0xffffffffu, ss, off);
    float inv = 1.0f / sqrtf(ss * (1.0f / HD) + 1e-6f);

    const float* cr = cosb + (size_t)tpos * HD;
    const float* sr = sinb + (size_t)tpos * HD;
    {
        int i2 = 2 * lane;
        float xr = w[i2] * v0.x * inv;
        float xi = w[i2 + 1] * v0.y * inv;
        float o0 = xr * cr[i2]     - xi * sr[i2];
        float o1 = xr * sr[i2 + 1] + xi * cr[i2 + 1];
        *(float2*)&row[i2] = make_float2(o0, o1);
    }
    if (lane < 16) {
        int i2 = 2 * (lane + 32);
        float xr = w[i2] * v1.x * inv;
        float xi = w[i2 + 1] * v1.y * inv;
        float o0 = xr * cr[i2]     - xi * sr[i2];
        float o1 = xr * sr[i2 + 1] + xi * cr[i2 + 1];
        *(float2*)&row[i2] = make_float2(o0, o1);
    }
}

// ---------------------------------------------------------------------------
// Flash-style causal attention, fp32.
// grid = (16 q-tiles, 32 heads, 2 batch), block = 256 threads.
// Q tile 64x96, K/V tiles 64x96 staged in smem, online softmax.
// ---------------------------------------------------------------------------
#define QTILE 64
#define ATTN_SMEM_FLOATS (HD*QTILE /*Qs*/ + HD*QTILE /*Ks*/ + QTILE*HD /*Vs*/ + QTILE*65 /*P*/ + 3*QTILE)
#define ATTN_SMEM_BYTES  (ATTN_SMEM_FLOATS * 4)

__global__ __launch_bounds__(256, 2)
void attn_kernel(const float* __restrict__ q, const float* __restrict__ k,
                 const float* __restrict__ v, float* __restrict__ o)
{
    extern __shared__ float sm[];
    float* Qs    = sm;                       // [HD][64]  (d-major)
    float* Ks    = Qs + HD * QTILE;          // [HD][64]
    float* Vs    = Ks + HD * QTILE;          // [64][HD]  (row-major)
    float* P     = Vs + QTILE * HD;          // [64][65]
    float* m_row = P + QTILE * 65;           // [64]
    float* l_row = m_row + QTILE;            // [64]
    float* alf   = l_row + QTILE;            // [64]

    const int qt = blockIdx.x;
    const int h  = blockIdx.y;
    const int b  = blockIdx.z;
    const int kv = h >> 2;
    const int t  = threadIdx.x;
    const int q0 = qt * QTILE;

    const float* qb = q + (size_t)b * TT * QDIM  + (size_t)h  * HD;
    const float* kb = k + (size_t)b * TT * KVDIM + (size_t)kv * HD;
    const float* vb = v + (size_t)b * TT * KVDIM + (size_t)kv * HD;
    float*       ob = o + (size_t)b * TT * QDIM  + (size_t)h  * HD;

    // Load Q tile transposed: Qs[d][r]
    for (int l = t; l < QTILE * HD; l += 256) {
        int r = l / HD, d = l % HD;
        Qs[d * QTILE + r] = qb[(size_t)(q0 + r) * QDIM + d];
    }
    if (t < QTILE) { m_row[t] = -1e30f; l_row[t] = 0.f; }

    const int r_c  = t >> 2;            // O-phase row (0..63)
    const int dbase = (t & 3) * 24;     // O-phase dim base
    float oacc[24];
#pragma unroll
    for (int i = 0; i < 24; i++) oacc[i] = 0.f;

    const float scale = 0.1020620726159658f;  // 1/sqrt(96)

    for (int kt = 0; kt <= qt; kt++) {
        __syncthreads();
        // Load K (transposed) and V tiles
        for (int l = t; l < QTILE * HD; l += 256) {
            int r = l / HD, d = l % HD;
            float kval = kb[(size_t)(kt * QTILE + r) * KVDIM + d];
            float vval = vb[(size_t)(kt * QTILE + r) * KVDIM + d];
            Ks[d * QTILE + r] = kval;
            Vs[r * HD + d]    = vval;
        }
        __syncthreads();

        // --- Phase A: S = scale * Q K^T, 4x4 register tile per thread ---
        {
            const int txa = t & 15, tya = t >> 4;
            const int r0 = tya * 4, j0 = txa * 4;
            float accS[4][4];
#pragma unroll
            for (int i = 0; i < 4; i++)
#pragma unroll
                for (int j = 0; j < 4; j++) accS[i][j] = 0.f;

#pragma unroll 4
            for (int d = 0; d < HD; d++) {
                float4 av = *(float4*)&Qs[d * QTILE + r0];
                float4 bv = *(float4*)&Ks[d * QTILE + j0];
                float a[4] = {av.x, av.y, av.z, av.w};
                float bb2[4] = {bv.x, bv.y, bv.z, bv.w};
#pragma unroll
                for (int i = 0; i < 4; i++)
#pragma unroll
                    for (int j = 0; j < 4; j++)
                        accS[i][j] += a[i] * bb2[j];
            }
#pragma unroll
            for (int i = 0; i < 4; i++) {
                int gq = q0 + r0 + i;
#pragma unroll
                for (int j = 0; j < 4; j++) {
                    int gk = kt * QTILE + j0 + j;
                    float val = accS[i][j] * scale;
                    if (gk > gq) val = -1e30f;
                    P[(r0 + i) * 65 + j0 + j] = val;
                }
            }
        }
        __syncthreads();

        // --- Phase B: online softmax stats per row (warp handles 8 rows) ---
        {
            const int w = t >> 5, lane = t & 31;
#pragma unroll
            for (int rr = 0; rr < 8; rr++) {
                int r = w * 8 + rr;
                float s0 = P[r * 65 + lane];
                float s1 = P[r * 65 + 32 + lane];
                float mx = fmaxf(s0, s1);
#pragma unroll
                for (int off = 16; off; off >>= 1)
                    mx = fmaxf(mx, __shfl_xor_sync(0xffffffffu, mx, off));
                float m_old = m_row[r];
                float m_new = fmaxf(m_old, mx);
                float p0 = __expf(s0 - m_new);
                float p1 = __expf(s1 - m_new);
                P[r * 65 + lane] = p0;
                P[r * 65 + 32 + lane] = p1;
                float sum = p0 + p1;
#pragma unroll
                for (int off = 16; off; off >>= 1)
                    sum += __shfl_xor_sync(0xffffffffu, sum, off);
                if (lane == 0) {
                    float al = __expf(m_old - m_new);
                    alf[r] = al;
                    l_row[r] = l_row[r] * al + sum;
                    m_row[r] = m_new;
                }
            }
        }
        __syncthreads();

        // --- Phase C: O = O*alpha + P V ---
        {
            float al = alf[r_c];
#pragma unroll
            for (int i = 0; i < 24; i++) oacc[i] *= al;
#pragma unroll 2
            for (int j = 0; j < QTILE; j++) {
                float p = P[r_c * 65 + j];
                const float* vr = &Vs[j * HD + dbase];
#pragma unroll
                for (int ii = 0; ii < 6; ii++) {
                    float4 vv = *(float4*)&vr[ii * 4];
                    oacc[ii*4+0] += p * vv.x;
                    oacc[ii*4+1] += p * vv.y;
                    oacc[ii*4+2] += p * vv.z;
                    oacc[ii*4+3] += p * vv.w;
                }
            }
        }
    }

    // Finalize: divide by l and write out (l_row was finalized before last sync)
    float invl = 1.0f / l_row[r_c];
    float* orow = &ob[(size_t)(q0 + r_c) * QDIM + dbase];
#pragma unroll
    for (int ii = 0; ii < 6; ii++) {
        float4 vv = make_float4(oacc[ii*4+0]*invl, oacc[ii*4+1]*invl,
                                oacc[ii*4+2]*invl, oacc[ii*4+3]*invl);
        *(float4*)&orow[ii * 4] = vv;
    }
}

// ---------------------------------------------------------------------------
// Launch
// ---------------------------------------------------------------------------
extern "C" void kernel_launch(void* const* d_in, const int* in_sizes, int n_in,
                              void* d_out, int out_size)
{
    const float* x    = (const float*)d_in[0];
    // d_in[1] is the mask (causal, handled analytically)
    const float* wq   = (const float*)d_in[2];
    const float* wk   = (const float*)d_in[3];
    const float* wv   = (const float*)d_in[4];
    const float* wo   = (const float*)d_in[5];
    const float* qnw  = (const float*)d_in[6];
    const float* knw  = (const float*)d_in[7];
    const float* cosb = (const float*)d_in[8];
    const float* sinb = (const float*)d_in[9];
    float* out = (float*)d_out;

    void *pq, *pk, *pv, *pa;
    cudaGetSymbolAddress(&pq, g_q);
    cudaGetSymbolAddress(&pk, g_k);
    cudaGetSymbolAddress(&pv, g_v);
    cudaGetSymbolAddress(&pa, g_attn);
    float* fq = (float*)pq;
    float* fk = (float*)pk;
    float* fv = (float*)pv;
    float* fa = (float*)pa;

    cudaFuncSetAttribute(attn_kernel, cudaFuncAttributeMaxDynamicSharedMemorySize,
                         ATTN_SMEM_BYTES);

    dim3 blk(256);

    // QKV projections
    sgemm_nt_kernel<<<dim3(QDIM / GT,  NTOK / GT), blk>>>(x, wq, fq, NTOK, QDIM,  DMODEL);
    sgemm_nt_kernel<<<dim3(KVDIM / GT, NTOK / GT), blk>>>(x, wk, fk, NTOK, KVDIM, DMODEL);
    sgemm_nt_kernel<<<dim3(KVDIM / GT, NTOK / GT), blk>>>(x, wv, fv, NTOK, KVDIM, DMODEL);

    // RMSNorm + RoPE on q and k
    {
        int rows_q = NTOK * NHEADS;
        int rows_k = NTOK * NKV;
        norm_rope_kernel<<<(rows_q * 32 + 255) / 256, blk>>>(fq, qnw, cosb, sinb, NHEADS, rows_q);
        norm_rope_kernel<<<(rows_k * 32 + 255) / 256, blk>>>(fk, knw, cosb, sinb, NKV, rows_k);
    }

    // Attention
    attn_kernel<<<dim3(TT / QTILE, NHEADS, BB), blk, ATTN_SMEM_BYTES>>>(fq, fk, fv, fa);

    // Output projection
    sgemm_nt_kernel<<<dim3(DMODEL / GT, NTOK / GT), blk>>>(fa, wo, out, NTOK, DMODEL, DMODEL);
}

// round 2
// speedup vs baseline: 1.4384x; 1.4384x over previous
#include <cuda_runtime.h>
#include <cuda_bf16.h>
#include <math.h>
#include <stdint.h>

// Problem constants
#define BB 2
#define TT 1024
#define DMODEL 3072
#define NHEADS 32
#define NKV 8
#define HD 96
#define NTOK (BB*TT)          // 2048
#define QDIM (NHEADS*HD)      // 3072
#define KVDIM (NKV*HD)        // 768

// Scratch (static device globals; no allocation allowed)
__device__ float g_q[NTOK*QDIM];
__device__ float g_k[NTOK*KVDIM];
__device__ float g_v[NTOK*KVDIM];
__device__ float g_attn[NTOK*QDIM];

__device__ __forceinline__ uint32_t f2tf32(float f) {
    uint32_t r;
    asm("cvt.rna.tf32.f32 %0, %1;" : "=r"(r) : "f"(f));
    return r;
}

// ---------------------------------------------------------------------------
// TF32 tensor-core GEMM: C[M,N] = A[M,K] * B[N,K]^T
// Block tile 128x128x32, 8 warps (2x4), warp tile 64x32, mma m16n8k8.
// Requires M%128==0, N%128==0, K%32==0.
// ---------------------------------------------------------------------------
__global__ __launch_bounds__(256)
void tf32_gemm_nt(const float* __restrict__ A, const float* __restrict__ B,
                  float* __restrict__ C, int M, int N, int K)
{
    __shared__ uint32_t As[128][33];
    __shared__ uint32_t Bs[128][33];

    const int tid = threadIdx.x;
    const int warp = tid >> 5;
    const int lane = tid & 31;
    const int g  = lane >> 2;   // groupID
    const int tg = lane & 3;    // threadID in group
    const int wm = warp & 1;    // 2 warps along M
    const int wn = warp >> 1;   // 4 warps along N
    const int m0 = blockIdx.y * 128;
    const int n0 = blockIdx.x * 128;

    float acc[4][4][4];
#pragma unroll
    for (int i = 0; i < 4; i++)
#pragma unroll
        for (int j = 0; j < 4; j++)
#pragma unroll
            for (int r = 0; r < 4; r++) acc[i][j][r] = 0.f;

    for (int k0 = 0; k0 < K; k0 += 32) {
        // Stage tiles: 128 rows x 32 k each = 1024 float4; 256 threads x 4.
#pragma unroll
        for (int i = 0; i < 4; i++) {
            int idx = tid + i * 256;
            int row = idx >> 3;
            int kc  = (idx & 7) * 4;
            float4 va = *(const float4*)&A[(size_t)(m0 + row) * K + k0 + kc];
            As[row][kc+0] = f2tf32(va.x); As[row][kc+1] = f2tf32(va.y);
            As[row][kc+2] = f2tf32(va.z); As[row][kc+3] = f2tf32(va.w);
            float4 vb = *(const float4*)&B[(size_t)(n0 + row) * K + k0 + kc];
            Bs[row][kc+0] = f2tf32(vb.x); Bs[row][kc+1] = f2tf32(vb.y);
            Bs[row][kc+2] = f2tf32(vb.z); Bs[row][kc+3] = f2tf32(vb.w);
        }
        __syncthreads();

#pragma unroll
        for (int ks = 0; ks < 32; ks += 8) {
            uint32_t afr[4][4], bfr[4][2];
#pragma unroll
            for (int mi = 0; mi < 4; mi++) {
                int rb = wm * 64 + mi * 16;
                afr[mi][0] = As[rb + g    ][ks + tg    ];
                afr[mi][1] = As[rb + g + 8][ks + tg    ];
                afr[mi][2] = As[rb + g    ][ks + tg + 4];
                afr[mi][3] = As[rb + g + 8][ks + tg + 4];
            }
#pragma unroll
            for (int ni = 0; ni < 4; ni++) {
                int nb = wn * 32 + ni * 8;
                bfr[ni][0] = Bs[nb + g][ks + tg    ];
                bfr[ni][1] = Bs[nb + g][ks + tg + 4];
            }
#pragma unroll
            for (int mi = 0; mi < 4; mi++)
#pragma unroll
                for (int ni = 0; ni < 4; ni++) {
                    asm volatile(
                        "mma.sync.aligned.m16n8k8.row.col.f32.tf32.tf32.f32 "
                        "{%0,%1,%2,%3}, {%4,%5,%6,%7}, {%8,%9}, {%0,%1,%2,%3};"
                        : "+f"(acc[mi][ni][0]), "+f"(acc[mi][ni][1]),
                          "+f"(acc[mi][ni][2]), "+f"(acc[mi][ni][3])
                        : "r"(afr[mi][0]), "r"(afr[mi][1]),
                          "r"(afr[mi][2]), "r"(afr[mi][3]),
                          "r"(bfr[ni][0]), "r"(bfr[ni][1]));
                }
        }
        __syncthreads();
    }

    // Epilogue
#pragma unroll
    for (int mi = 0; mi < 4; mi++) {
        int row = m0 + wm * 64 + mi * 16 + g;
#pragma unroll
        for (int ni = 0; ni < 4; ni++) {
            int col = n0 + wn * 32 + ni * 8 + 2 * tg;
            *(float2*)&C[(size_t)row * N + col] =
                make_float2(acc[mi][ni][0], acc[mi][ni][1]);
            *(float2*)&C[(size_t)(row + 8) * N + col] =
                make_float2(acc[mi][ni][2], acc[mi][ni][3]);
        }
    }
}

// ---------------------------------------------------------------------------
// Fused RMSNorm + RoPE (in place). One warp per (token, head).
// ---------------------------------------------------------------------------
__global__ void norm_rope_kernel(float* __restrict__ buf,
                                 const float* __restrict__ w,
                                 const float* __restrict__ cosb,
                                 const float* __restrict__ sinb,
                                 int H, int total_rows)
{
    int gw = (blockIdx.x * blockDim.x + threadIdx.x) >> 5;
    if (gw >= total_rows) return;
    int lane = threadIdx.x & 31;
    int h   = gw % H;
    int tok = gw / H;
    int tpos = tok & (TT - 1);
    float* row = buf + (size_t)tok * H * HD + (size_t)h * HD;

    float2 v0 = *(float2*)&row[2 * lane];
    float2 v1 = make_float2(0.f, 0.f);
    if (lane < 16) v1 = *(float2*)&row[2 * (lane + 32)];

    float ss = v0.x*v0.x + v0.y*v0.y + v1.x*v1.x + v1.y*v1.y;
#pragma unroll
    for (int off = 16; off; off >>= 1)
        ss += __shfl_xor_sync(0xffffffffu, ss, off);
    float inv = 1.0f / sqrtf(ss * (1.0f / HD) + 1e-6f);

    const float* cr = cosb + (size_t)tpos * HD;
    const float* sr = sinb + (size_t)tpos * HD;
    {
        int i2 = 2 * lane;
        float xr = w[i2] * v0.x * inv;
        float xi = w[i2 + 1] * v0.y * inv;
        float o0 = xr * cr[i2]     - xi * sr[i2];
        float o1 = xr * sr[i2 + 1] + xi * cr[i2 + 1];
        *(float2*)&row[i2] = make_float2(o0, o1);
    }
    if (lane < 16) {
        int i2 = 2 * (lane + 32);
        float xr = w[i2] * v1.x * inv;
        float xi = w[i2 + 1] * v1.y * inv;
        float o0 = xr * cr[i2]     - xi * sr[i2];
        float o1 = xr * sr[i2 + 1] + xi * cr[i2 + 1];
        *(float2*)&row[i2] = make_float2(o0, o1);
    }
}

// ---------------------------------------------------------------------------
// Flash-style causal attention, fp32. (unchanged this round)
// ---------------------------------------------------------------------------
#define QTILE 64
#define ATTN_SMEM_FLOATS (HD*QTILE + HD*QTILE + QTILE*HD + QTILE*65 + 3*QTILE)
#define ATTN_SMEM_BYTES  (ATTN_SMEM_FLOATS * 4)

__global__ __launch_bounds__(256, 2)
void attn_kernel(const float* __restrict__ q, const float* __restrict__ k,
                 const float* __restrict__ v, float* __restrict__ o)
{
    extern __shared__ float sm[];
    float* Qs    = sm;
    float* Ks    = Qs + HD * QTILE;
    float* Vs    = Ks + HD * QTILE;
    float* P     = Vs + QTILE * HD;
    float* m_row = P + QTILE * 65;
    float* l_row = m_row + QTILE;
    float* alf   = l_row + QTILE;

    const int qt = blockIdx.x;
    const int h  = blockIdx.y;
    const int b  = blockIdx.z;
    const int kv = h >> 2;
    const int t  = threadIdx.x;
    const int q0 = qt * QTILE;

    const float* qb = q + (size_t)b * TT * QDIM  + (size_t)h  * HD;
    const float* kb = k + (size_t)b * TT * KVDIM + (size_t)kv * HD;
    const float* vb = v + (size_t)b * TT * KVDIM + (size_t)kv * HD;
    float*       ob = o + (size_t)b * TT * QDIM  + (size_t)h  * HD;

    for (int l = t; l < QTILE * HD; l += 256) {
        int r = l / HD, d = l % HD;
        Qs[d * QTILE + r] = qb[(size_t)(q0 + r) * QDIM + d];
    }
    if (t < QTILE) { m_row[t] = -1e30f; l_row[t] = 0.f; }

    const int r_c  = t >> 2;
    const int dbase = (t & 3) * 24;
    float oacc[24];
#pragma unroll
    for (int i = 0; i < 24; i++) oacc[i] = 0.f;

    const float scale = 0.1020620726159658f;

    for (int kt = 0; kt <= qt; kt++) {
        __syncthreads();
        for (int l = t; l < QTILE * HD; l += 256) {
            int r = l / HD, d = l % HD;
            float kval = kb[(size_t)(kt * QTILE + r) * KVDIM + d];
            float vval = vb[(size_t)(kt * QTILE + r) * KVDIM + d];
            Ks[d * QTILE + r] = kval;
            Vs[r * HD + d]    = vval;
        }
        __syncthreads();

        {
            const int txa = t & 15, tya = t >> 4;
            const int r0 = tya * 4, j0 = txa * 4;
            float accS[4][4];
#pragma unroll
            for (int i = 0; i < 4; i++)
#pragma unroll
                for (int j = 0; j < 4; j++) accS[i][j] = 0.f;

#pragma unroll 4
            for (int d = 0; d < HD; d++) {
                float4 av = *(float4*)&Qs[d * QTILE + r0];
                float4 bv = *(float4*)&Ks[d * QTILE + j0];
                float a[4] = {av.x, av.y, av.z, av.w};
                float bb2[4] = {bv.x, bv.y, bv.z, bv.w};
#pragma unroll
                for (int i = 0; i < 4; i++)
#pragma unroll
                    for (int j = 0; j < 4; j++)
                        accS[i][j] += a[i] * bb2[j];
            }
#pragma unroll
            for (int i = 0; i < 4; i++) {
                int gq = q0 + r0 + i;
#pragma unroll
                for (int j = 0; j < 4; j++) {
                    int gk = kt * QTILE + j0 + j;
                    float val = accS[i][j] * scale;
                    if (gk > gq) val = -1e30f;
                    P[(r0 + i) * 65 + j0 + j] = val;
                }
            }
        }
        __syncthreads();

        {
            const int w = t >> 5, lane = t & 31;
#pragma unroll
            for (int rr = 0; rr < 8; rr++) {
                int r = w * 8 + rr;
                float s0 = P[r * 65 + lane];
                float s1 = P[r * 65 + 32 + lane];
                float mx = fmaxf(s0, s1);
#pragma unroll
                for (int off = 16; off; off >>= 1)
                    mx = fmaxf(mx, __shfl_xor_sync(0xffffffffu, mx, off));
                float m_old = m_row[r];
                float m_new = fmaxf(m_old, mx);
                float p0 = __expf(s0 - m_new);
                float p1 = __expf(s1 - m_new);
                P[r * 65 + lane] = p0;
                P[r * 65 + 32 + lane] = p1;
                float sum = p0 + p1;
#pragma unroll
                for (int off = 16; off; off >>= 1)
                    sum += __shfl_xor_sync(0xffffffffu, sum, off);
                if (lane == 0) {
                    float al = __expf(m_old - m_new);
                    alf[r] = al;
                    l_row[r] = l_row[r] * al + sum;
                    m_row[r] = m_new;
                }
            }
        }
        __syncthreads();

        {
            float al = alf[r_c];
#pragma unroll
            for (int i = 0; i < 24; i++) oacc[i] *= al;
#pragma unroll 2
            for (int j = 0; j < QTILE; j++) {
                float p = P[r_c * 65 + j];
                const float* vr = &Vs[j * HD + dbase];
#pragma unroll
                for (int ii = 0; ii < 6; ii++) {
                    float4 vv = *(float4*)&vr[ii * 4];
                    oacc[ii*4+0] += p * vv.x;
                    oacc[ii*4+1] += p * vv.y;
                    oacc[ii*4+2] += p * vv.z;
                    oacc[ii*4+3] += p * vv.w;
                }
            }
        }
    }

    float invl = 1.0f / l_row[r_c];
    float* orow = &ob[(size_t)(q0 + r_c) * QDIM + dbase];
#pragma unroll
    for (int ii = 0; ii < 6; ii++) {
        float4 vv = make_float4(oacc[ii*4+0]*invl, oacc[ii*4+1]*invl,
                                oacc[ii*4+2]*invl, oacc[ii*4+3]*invl);
        *(float4*)&orow[ii * 4] = vv;
    }
}

// ---------------------------------------------------------------------------
// Launch
// ---------------------------------------------------------------------------
extern "C" void kernel_launch(void* const* d_in, const int* in_sizes, int n_in,
                              void* d_out, int out_size)
{
    const float* x    = (const float*)d_in[0];
    const float* wq   = (const float*)d_in[2];
    const float* wk   = (const float*)d_in[3];
    const float* wv   = (const float*)d_in[4];
    const float* wo   = (const float*)d_in[5];
    const float* qnw  = (const float*)d_in[6];
    const float* knw  = (const float*)d_in[7];
    const float* cosb = (const float*)d_in[8];
    const float* sinb = (const float*)d_in[9];
    float* out = (float*)d_out;

    void *pq, *pk, *pv, *pa;
    cudaGetSymbolAddress(&pq, g_q);
    cudaGetSymbolAddress(&pk, g_k);
    cudaGetSymbolAddress(&pv, g_v);
    cudaGetSymbolAddress(&pa, g_attn);
    float* fq = (float*)pq;
    float* fk = (float*)pk;
    float* fv = (float*)pv;
    float* fa = (float*)pa;

    cudaFuncSetAttribute(attn_kernel, cudaFuncAttributeMaxDynamicSharedMemorySize,
                         ATTN_SMEM_BYTES);

    dim3 blk(256);

    // QKV projections (TF32 tensor cores)
    tf32_gemm_nt<<<dim3(QDIM / 128,  NTOK / 128), blk>>>(x, wq, fq, NTOK, QDIM,  DMODEL);
    tf32_gemm_nt<<<dim3(KVDIM / 128, NTOK / 128), blk>>>(x, wk, fk, NTOK, KVDIM, DMODEL);
    tf32_gemm_nt<<<dim3(KVDIM / 128, NTOK / 128), blk>>>(x, wv, fv, NTOK, KVDIM, DMODEL);

    // RMSNorm + RoPE on q and k
    {
        int rows_q = NTOK * NHEADS;
        int rows_k = NTOK * NKV;
        norm_rope_kernel<<<(rows_q * 32 + 255) / 256, blk>>>(fq, qnw, cosb, sinb, NHEADS, rows_q);
        norm_rope_kernel<<<(rows_k * 32 + 255) / 256, blk>>>(fk, knw, cosb, sinb, NKV, rows_k);
    }

    // Attention
    attn_kernel<<<dim3(TT / QTILE, NHEADS, BB), blk, ATTN_SMEM_BYTES>>>(fq, fk, fv, fa);

    // Output projection (TF32 tensor cores)
    tf32_gemm_nt<<<dim3(DMODEL / 128, NTOK / 128), blk>>>(fa, wo, out, NTOK, DMODEL, DMODEL);
}

// round 3
// speedup vs baseline: 3.4206x; 2.3781x over previous
#include <cuda_runtime.h>
#include <cuda_bf16.h>
#include <math.h>
#include <stdint.h>

// Problem constants
#define BB 2
#define TT 1024
#define DMODEL 3072
#define NHEADS 32
#define NKV 8
#define HD 96
#define NTOK (BB*TT)          // 2048
#define QDIM (NHEADS*HD)      // 3072
#define KVDIM (NKV*HD)        // 768

// Scratch (static device globals; no allocation allowed)
__device__ float g_q[NTOK*QDIM];
__device__ float g_k[NTOK*KVDIM];
__device__ float g_v[NTOK*KVDIM];
__device__ float g_attn[NTOK*QDIM];
// tf32-rounded operand copies
__device__ float g_xr[NTOK*DMODEL];
__device__ float g_wqr[QDIM*DMODEL];
__device__ float g_wkr[KVDIM*DMODEL];
__device__ float g_wvr[KVDIM*DMODEL];
__device__ float g_wor[DMODEL*QDIM];

__device__ __forceinline__ float f2tf32f(float f) {
    uint32_t r;
    asm("cvt.rna.tf32.f32 %0, %1;" : "=r"(r) : "f"(f));
    return __uint_as_float(r);
}

// ---------------------------------------------------------------------------
// Element-wise tf32 rounding pass (vectorized)
// ---------------------------------------------------------------------------
__global__ void tf32_round_kernel(const float* __restrict__ in,
                                  float* __restrict__ out, int n4)
{
    int i = blockIdx.x * blockDim.x + threadIdx.x;
    if (i >= n4) return;
    float4 v = ((const float4*)in)[i];
    v.x = f2tf32f(v.x); v.y = f2tf32f(v.y);
    v.z = f2tf32f(v.z); v.w = f2tf32f(v.w);
    ((float4*)out)[i] = v;
}

// ---------------------------------------------------------------------------
// TF32 tensor-core GEMM with cp.async double buffering.
// C[M,N] = A[M,K] * B[N,K]^T. Inputs must already be tf32-rounded.
// Block tile 128x128x32, 8 warps (2x4), warp tile 64x32, mma m16n8k8.
// ---------------------------------------------------------------------------
#define BMT 128
#define BKT 32
#define PADW 36                      // floats per smem row (144B, 9x16B)
#define STAGEF (2 * BMT * PADW)      // floats per stage (A+B)
#define GEMM_SMEM_BYTES (2 * STAGEF * 4)

__global__ __launch_bounds__(256)
void tf32_gemm_db(const float* __restrict__ A, const float* __restrict__ B,
                  float* __restrict__ C, int M, int N, int K)
{
    extern __shared__ float sm[];

    const int tid = threadIdx.x;
    const int warp = tid >> 5;
    const int lane = tid & 31;
    const int g  = lane >> 2;
    const int tg = lane & 3;
    const int wm = warp & 1;
    const int wn = warp >> 1;
    const int m0 = blockIdx.y * BMT;
    const int n0 = blockIdx.x * BMT;

    const int lrow = tid >> 3;          // 0..31? no: tid/8 -> 0..31 for 256 threads? 256/8=32 rows per pass
    const int lk4  = (tid & 7) * 4;

    float acc[4][4][4];
#pragma unroll
    for (int i = 0; i < 4; i++)
#pragma unroll
        for (int j = 0; j < 4; j++)
#pragma unroll
            for (int r = 0; r < 4; r++) acc[i][j][r] = 0.f;

    const int nkt = K / BKT;

    // stage loader: 128 rows x 32 floats per matrix = 1024 16B chunks each
    auto load_stage = [&](int s, int k0) {
        float* dstA = sm + s * STAGEF;
        float* dstB = dstA + BMT * PADW;
#pragma unroll
        for (int i = 0; i < 4; i++) {
            int row = lrow + i * 32;
            uint32_t da = (uint32_t)__cvta_generic_to_shared(&dstA[row * PADW + lk4]);
            const float* ga = &A[(size_t)(m0 + row) * K + k0 + lk4];
            asm volatile("cp.async.cg.shared.global [%0], [%1], 16;" :: "r"(da), "l"(ga));
            uint32_t db = (uint32_t)__cvta_generic_to_shared(&dstB[row * PADW + lk4]);
            const float* gb = &B[(size_t)(n0 + row) * K + k0 + lk4];
            asm volatile("cp.async.cg.shared.global [%0], [%1], 16;" :: "r"(db), "l"(gb));
        }
    };

    load_stage(0, 0);
    asm volatile("cp.async.commit_group;");

    for (int kt = 0; kt < nkt; kt++) {
        int cur = kt & 1;
        if (kt + 1 < nkt) {
            load_stage(cur ^ 1, (kt + 1) * BKT);
            asm volatile("cp.async.commit_group;");
            asm volatile("cp.async.wait_group 1;");
        } else {
            asm volatile("cp.async.wait_group 0;");
        }
        __syncthreads();

        const uint32_t* As = (const uint32_t*)(sm + cur * STAGEF);
        const uint32_t* Bs = As + BMT * PADW;

#pragma unroll
        for (int ks = 0; ks < BKT; ks += 8) {
            uint32_t afr[4][4], bfr[4][2];
#pragma unroll
            for (int mi = 0; mi < 4; mi++) {
                int rb = wm * 64 + mi * 16;
                afr[mi][0] = As[(rb + g    ) * PADW + ks + tg    ];
                afr[mi][1] = As[(rb + g + 8) * PADW + ks + tg    ];
                afr[mi][2] = As[(rb + g    ) * PADW + ks + tg + 4];
                afr[mi][3] = As[(rb + g + 8) * PADW + ks + tg + 4];
            }
#pragma unroll
            for (int ni = 0; ni < 4; ni++) {
                int nb = wn * 32 + ni * 8;
                bfr[ni][0] = Bs[(nb + g) * PADW + ks + tg    ];
                bfr[ni][1] = Bs[(nb + g) * PADW + ks + tg + 4];
            }
#pragma unroll
            for (int mi = 0; mi < 4; mi++)
#pragma unroll
                for (int ni = 0; ni < 4; ni++) {
                    asm volatile(
                        "mma.sync.aligned.m16n8k8.row.col.f32.tf32.tf32.f32 "
                        "{%0,%1,%2,%3}, {%4,%5,%6,%7}, {%8,%9}, {%0,%1,%2,%3};"
                        : "+f"(acc[mi][ni][0]), "+f"(acc[mi][ni][1]),
                          "+f"(acc[mi][ni][2]), "+f"(acc[mi][ni][3])
                        : "r"(afr[mi][0]), "r"(afr[mi][1]),
                          "r"(afr[mi][2]), "r"(afr[mi][3]),
                          "r"(bfr[ni][0]), "r"(bfr[ni][1]));
                }
        }
        __syncthreads();
    }

#pragma unroll
    for (int mi = 0; mi < 4; mi++) {
        int row = m0 + wm * 64 + mi * 16 + g;
#pragma unroll
        for (int ni = 0; ni < 4; ni++) {
            int col = n0 + wn * 32 + ni * 8 + 2 * tg;
            *(float2*)&C[(size_t)row * N + col] =
                make_float2(acc[mi][ni][0], acc[mi][ni][1]);
            *(float2*)&C[(size_t)(row + 8) * N + col] =
                make_float2(acc[mi][ni][2], acc[mi][ni][3]);
        }
    }
}

// ---------------------------------------------------------------------------
// Fused RMSNorm + RoPE (in place). One warp per (token, head).
// ---------------------------------------------------------------------------
__global__ void norm_rope_kernel(float* __restrict__ buf,
                                 const float* __restrict__ w,
                                 const float* __restrict__ cosb,
                                 const float* __restrict__ sinb,
                                 int H, int total_rows)
{
    int gw = (blockIdx.x * blockDim.x + threadIdx.x) >> 5;
    if (gw >= total_rows) return;
    int lane = threadIdx.x & 31;
    int h   = gw % H;
    int tok = gw / H;
    int tpos = tok & (TT - 1);
    float* row = buf + (size_t)tok * H * HD + (size_t)h * HD;

    float2 v0 = *(float2*)&row[2 * lane];
    float2 v1 = make_float2(0.f, 0.f);
    if (lane < 16) v1 = *(float2*)&row[2 * (lane + 32)];

    float ss = v0.x*v0.x + v0.y*v0.y + v1.x*v1.x + v1.y*v1.y;
#pragma unroll
    for (int off = 16; off; off >>= 1)
        ss += __shfl_xor_sync(0xffffffffu, ss, off);
    float inv = 1.0f / sqrtf(ss * (1.0f / HD) + 1e-6f);

    const float* cr = cosb + (size_t)tpos * HD;
    const float* sr = sinb + (size_t)tpos * HD;
    {
        int i2 = 2 * lane;
        float xr = w[i2] * v0.x * inv;
        float xi = w[i2 + 1] * v0.y * inv;
        float o0 = xr * cr[i2]     - xi * sr[i2];
        float o1 = xr * sr[i2 + 1] + xi * cr[i2 + 1];
        *(float2*)&row[i2] = make_float2(o0, o1);
    }
    if (lane < 16) {
        int i2 = 2 * (lane + 32);
        float xr = w[i2] * v1.x * inv;
        float xi = w[i2 + 1] * v1.y * inv;
        float o0 = xr * cr[i2]     - xi * sr[i2];
        float o1 = xr * sr[i2 + 1] + xi * cr[i2 + 1];
        *(float2*)&row[i2] = make_float2(o0, o1);
    }
}

// ---------------------------------------------------------------------------
// Flash-style causal attention, fp32. Output rounded to tf32 for wo GEMM.
// ---------------------------------------------------------------------------
#define QTILE 64
#define ATTN_SMEM_FLOATS (HD*QTILE + HD*QTILE + QTILE*HD + QTILE*65 + 3*QTILE)
#define ATTN_SMEM_BYTES  (ATTN_SMEM_FLOATS * 4)

__global__ __launch_bounds__(256, 2)
void attn_kernel(const float* __restrict__ q, const float* __restrict__ k,
                 const float* __restrict__ v, float* __restrict__ o)
{
    extern __shared__ float sm[];
    float* Qs    = sm;
    float* Ks    = Qs + HD * QTILE;
    float* Vs    = Ks + HD * QTILE;
    float* P     = Vs + QTILE * HD;
    float* m_row = P + QTILE * 65;
    float* l_row = m_row + QTILE;
    float* alf   = l_row + QTILE;

    const int qt = blockIdx.x;
    const int h  = blockIdx.y;
    const int b  = blockIdx.z;
    const int kv = h >> 2;
    const int t  = threadIdx.x;
    const int q0 = qt * QTILE;

    const float* qb = q + (size_t)b * TT * QDIM  + (size_t)h  * HD;
    const float* kb = k + (size_t)b * TT * KVDIM + (size_t)kv * HD;
    const float* vb = v + (size_t)b * TT * KVDIM + (size_t)kv * HD;
    float*       ob = o + (size_t)b * TT * QDIM  + (size_t)h  * HD;

    for (int l = t; l < QTILE * HD; l += 256) {
        int r = l / HD, d = l % HD;
        Qs[d * QTILE + r] = qb[(size_t)(q0 + r) * QDIM + d];
    }
    if (t < QTILE) { m_row[t] = -1e30f; l_row[t] = 0.f; }

    const int r_c  = t >> 2;
    const int dbase = (t & 3) * 24;
    float oacc[24];
#pragma unroll
    for (int i = 0; i < 24; i++) oacc[i] = 0.f;

    const float scale = 0.1020620726159658f;

    for (int kt = 0; kt <= qt; kt++) {
        __syncthreads();
        for (int l = t; l < QTILE * HD; l += 256) {
            int r = l / HD, d = l % HD;
            float kval = kb[(size_t)(kt * QTILE + r) * KVDIM + d];
            float vval = vb[(size_t)(kt * QTILE + r) * KVDIM + d];
            Ks[d * QTILE + r] = kval;
            Vs[r * HD + d]    = vval;
        }
        __syncthreads();

        {
            const int txa = t & 15, tya = t >> 4;
            const int r0 = tya * 4, j0 = txa * 4;
            float accS[4][4];
#pragma unroll
            for (int i = 0; i < 4; i++)
#pragma unroll
                for (int j = 0; j < 4; j++) accS[i][j] = 0.f;

#pragma unroll 4
            for (int d = 0; d < HD; d++) {
                float4 av = *(float4*)&Qs[d * QTILE + r0];
                float4 bv = *(float4*)&Ks[d * QTILE + j0];
                float a[4] = {av.x, av.y, av.z, av.w};
                float bb2[4] = {bv.x, bv.y, bv.z, bv.w};
#pragma unroll
                for (int i = 0; i < 4; i++)
#pragma unroll
                    for (int j = 0; j < 4; j++)
                        accS[i][j] += a[i] * bb2[j];
            }
#pragma unroll
            for (int i = 0; i < 4; i++) {
                int gq = q0 + r0 + i;
#pragma unroll
                for (int j = 0; j < 4; j++) {
                    int gk = kt * QTILE + j0 + j;
                    float val = accS[i][j] * scale;
                    if (gk > gq) val = -1e30f;
                    P[(r0 + i) * 65 + j0 + j] = val;
                }
            }
        }
        __syncthreads();

        {
            const int w = t >> 5, lane = t & 31;
#pragma unroll
            for (int rr = 0; rr < 8; rr++) {
                int r = w * 8 + rr;
                float s0 = P[r * 65 + lane];
                float s1 = P[r * 65 + 32 + lane];
                float mx = fmaxf(s0, s1);
#pragma unroll
                for (int off = 16; off; off >>= 1)
                    mx = fmaxf(mx, __shfl_xor_sync(0xffffffffu, mx, off));
                float m_old = m_row[r];
                float m_new = fmaxf(m_old, mx);
                float p0 = __expf(s0 - m_new);
                float p1 = __expf(s1 - m_new);
                P[r * 65 + lane] = p0;
                P[r * 65 + 32 + lane] = p1;
                float sum = p0 + p1;
#pragma unroll
                for (int off = 16; off; off >>= 1)
                    sum += __shfl_xor_sync(0xffffffffu, sum, off);
                if (lane == 0) {
                    float al = __expf(m_old - m_new);
                    alf[r] = al;
                    l_row[r] = l_row[r] * al + sum;
                    m_row[r] = m_new;
                }
            }
        }
        __syncthreads();

        {
            float al = alf[r_c];
#pragma unroll
            for (int i = 0; i < 24; i++) oacc[i] *= al;
#pragma unroll 2
            for (int j = 0; j < QTILE; j++) {
                float p = P[r_c * 65 + j];
                const float* vr = &Vs[j * HD + dbase];
#pragma unroll
                for (int ii = 0; ii < 6; ii++) {
                    float4 vv = *(float4*)&vr[ii * 4];
                    oacc[ii*4+0] += p * vv.x;
                    oacc[ii*4+1] += p * vv.y;
                    oacc[ii*4+2] += p * vv.z;
                    oacc[ii*4+3] += p * vv.w;
                }
            }
        }
    }

    // Finalize: divide by l, round to tf32 (consumed by wo mma), write out.
    float invl = 1.0f / l_row[r_c];
    float* orow = &ob[(size_t)(q0 + r_c) * QDIM + dbase];
#pragma unroll
    for (int ii = 0; ii < 6; ii++) {
        float4 vv = make_float4(f2tf32f(oacc[ii*4+0]*invl), f2tf32f(oacc[ii*4+1]*invl),
                                f2tf32f(oacc[ii*4+2]*invl), f2tf32f(oacc[ii*4+3]*invl));
        *(float4*)&orow[ii * 4] = vv;
    }
}

// ---------------------------------------------------------------------------
// Launch
// ---------------------------------------------------------------------------
extern "C" void kernel_launch(void* const* d_in, const int* in_sizes, int n_in,
                              void* d_out, int out_size)
{
    const float* x    = (const float*)d_in[0];
    const float* wq   = (const float*)d_in[2];
    const float* wk   = (const float*)d_in[3];
    const float* wv   = (const float*)d_in[4];
    const float* wo   = (const float*)d_in[5];
    const float* qnw  = (const float*)d_in[6];
    const float* knw  = (const float*)d_in[7];
    const float* cosb = (const float*)d_in[8];
    const float* sinb = (const float*)d_in[9];
    float* out = (float*)d_out;

    void *pq, *pk, *pv, *pa, *pxr, *pwq, *pwk, *pwv, *pwo;
    cudaGetSymbolAddress(&pq, g_q);
    cudaGetSymbolAddress(&pk, g_k);
    cudaGetSymbolAddress(&pv, g_v);
    cudaGetSymbolAddress(&pa, g_attn);
    cudaGetSymbolAddress(&pxr, g_xr);
    cudaGetSymbolAddress(&pwq, g_wqr);
    cudaGetSymbolAddress(&pwk, g_wkr);
    cudaGetSymbolAddress(&pwv, g_wvr);
    cudaGetSymbolAddress(&pwo, g_wor);
    float* fq = (float*)pq;   float* fk = (float*)pk;
    float* fv = (float*)pv;   float* fa = (float*)pa;
    float* fxr = (float*)pxr; float* fwq = (float*)pwq;
    float* fwk = (float*)pwk; float* fwv = (float*)pwv;
    float* fwo = (float*)pwo;

    cudaFuncSetAttribute(attn_kernel, cudaFuncAttributeMaxDynamicSharedMemorySize,
                         ATTN_SMEM_BYTES);
    cudaFuncSetAttribute(tf32_gemm_db, cudaFuncAttributeMaxDynamicSharedMemorySize,
                         GEMM_SMEM_BYTES);

    dim3 blk(256);

    // tf32 rounding pre-passes
    {
        int n;
        n = NTOK * DMODEL / 4;  tf32_round_kernel<<<(n+255)/256, blk>>>(x,  fxr, n);
        n = QDIM * DMODEL / 4;  tf32_round_kernel<<<(n+255)/256, blk>>>(wq, fwq, n);
        n = KVDIM * DMODEL / 4; tf32_round_kernel<<<(n+255)/256, blk>>>(wk, fwk, n);
        n = KVDIM * DMODEL / 4; tf32_round_kernel<<<(n+255)/256, blk>>>(wv, fwv, n);
        n = DMODEL * QDIM / 4;  tf32_round_kernel<<<(n+255)/256, blk>>>(wo, fwo, n);
    }

    // QKV projections (TF32 tensor cores, double-buffered)
    tf32_gemm_db<<<dim3(QDIM / 128,  NTOK / 128), blk, GEMM_SMEM_BYTES>>>(fxr, fwq, fq, NTOK, QDIM,  DMODEL);
    tf32_gemm_db<<<dim3(KVDIM / 128, NTOK / 128), blk, GEMM_SMEM_BYTES>>>(fxr, fwk, fk, NTOK, KVDIM, DMODEL);
    tf32_gemm_db<<<dim3(KVDIM / 128, NTOK / 128), blk, GEMM_SMEM_BYTES>>>(fxr, fwv, fv, NTOK, KVDIM, DMODEL);

    // RMSNorm + RoPE on q and k
    {
        int rows_q = NTOK * NHEADS;
        int rows_k = NTOK * NKV;
        norm_rope_kernel<<<(rows_q * 32 + 255) / 256, blk>>>(fq, qnw, cosb, sinb, NHEADS, rows_q);
        norm_rope_kernel<<<(rows_k * 32 + 255) / 256, blk>>>(fk, knw, cosb, sinb, NKV, rows_k);
    }

    // Attention
    attn_kernel<<<dim3(TT / QTILE, NHEADS, BB), blk, ATTN_SMEM_BYTES>>>(fq, fk, fv, fa);

    // Output projection (TF32 tensor cores, double-buffered)
    tf32_gemm_db<<<dim3(DMODEL / 128, NTOK / 128), blk, GEMM_SMEM_BYTES>>>(fa, fwo, out, NTOK, DMODEL, DMODEL);
}

// round 4
// speedup vs baseline: 6.3054x; 1.8434x over previous
#include <cuda_runtime.h>
#include <cuda_bf16.h>
#include <math.h>
#include <stdint.h>

// Problem constants
#define BB 2
#define TT 1024
#define DMODEL 3072
#define NHEADS 32
#define NKV 8
#define HD 96
#define NTOK (BB*TT)          // 2048
#define QDIM (NHEADS*HD)      // 3072
#define KVDIM (NKV*HD)        // 768

// Scratch (static device globals; no allocation allowed)
__device__ float g_q[NTOK*QDIM];
__device__ float g_k[NTOK*KVDIM];
__device__ float g_v[NTOK*KVDIM];
__device__ float g_attn[NTOK*QDIM];
// tf32-rounded operand copies
__device__ float g_xr[NTOK*DMODEL];
__device__ float g_wqr[QDIM*DMODEL];
__device__ float g_wkr[KVDIM*DMODEL];
__device__ float g_wvr[KVDIM*DMODEL];
__device__ float g_wor[DMODEL*QDIM];

__device__ __forceinline__ float f2tf32f(float f) {
    uint32_t r;
    asm("cvt.rna.tf32.f32 %0, %1;" : "=r"(r) : "f"(f));
    return __uint_as_float(r);
}
__device__ __forceinline__ uint32_t f2tf32u(float f) {
    uint32_t r;
    asm("cvt.rna.tf32.f32 %0, %1;" : "=r"(r) : "f"(f));
    return r;
}

#define MMA_TF32(acc, a0,a1,a2,a3, b0,b1)                                     \
    asm volatile(                                                             \
        "mma.sync.aligned.m16n8k8.row.col.f32.tf32.tf32.f32 "                 \
        "{%0,%1,%2,%3}, {%4,%5,%6,%7}, {%8,%9}, {%0,%1,%2,%3};"               \
        : "+f"(acc[0]), "+f"(acc[1]), "+f"(acc[2]), "+f"(acc[3])              \
        : "r"(a0), "r"(a1), "r"(a2), "r"(a3), "r"(b0), "r"(b1))

// ---------------------------------------------------------------------------
// Element-wise tf32 rounding pass (vectorized)
// ---------------------------------------------------------------------------
__global__ void tf32_round_kernel(const float* __restrict__ in,
                                  float* __restrict__ out, int n4)
{
    int i = blockIdx.x * blockDim.x + threadIdx.x;
    if (i >= n4) return;
    float4 v = ((const float4*)in)[i];
    v.x = f2tf32f(v.x); v.y = f2tf32f(v.y);
    v.z = f2tf32f(v.z); v.w = f2tf32f(v.w);
    ((float4*)out)[i] = v;
}

// ---------------------------------------------------------------------------
// TF32 tensor-core GEMM with cp.async double buffering. (unchanged)
// ---------------------------------------------------------------------------
#define BMT 128
#define BKT 32
#define PADW 36
#define STAGEF (2 * BMT * PADW)
#define GEMM_SMEM_BYTES (2 * STAGEF * 4)

__global__ __launch_bounds__(256)
void tf32_gemm_db(const float* __restrict__ A, const float* __restrict__ B,
                  float* __restrict__ C, int M, int N, int K)
{
    extern __shared__ float sm[];

    const int tid = threadIdx.x;
    const int warp = tid >> 5;
    const int lane = tid & 31;
    const int g  = lane >> 2;
    const int tg = lane & 3;
    const int wm = warp & 1;
    const int wn = warp >> 1;
    const int m0 = blockIdx.y * BMT;
    const int n0 = blockIdx.x * BMT;

    const int lrow = tid >> 3;
    const int lk4  = (tid & 7) * 4;

    float acc[4][4][4];
#pragma unroll
    for (int i = 0; i < 4; i++)
#pragma unroll
        for (int j = 0; j < 4; j++)
#pragma unroll
            for (int r = 0; r < 4; r++) acc[i][j][r] = 0.f;

    const int nkt = K / BKT;

    auto load_stage = [&](int s, int k0) {
        float* dstA = sm + s * STAGEF;
        float* dstB = dstA + BMT * PADW;
#pragma unroll
        for (int i = 0; i < 4; i++) {
            int row = lrow + i * 32;
            uint32_t da = (uint32_t)__cvta_generic_to_shared(&dstA[row * PADW + lk4]);
            const float* ga = &A[(size_t)(m0 + row) * K + k0 + lk4];
            asm volatile("cp.async.cg.shared.global [%0], [%1], 16;" :: "r"(da), "l"(ga));
            uint32_t db = (uint32_t)__cvta_generic_to_shared(&dstB[row * PADW + lk4]);
            const float* gb = &B[(size_t)(n0 + row) * K + k0 + lk4];
            asm volatile("cp.async.cg.shared.global [%0], [%1], 16;" :: "r"(db), "l"(gb));
        }
    };

    load_stage(0, 0);
    asm volatile("cp.async.commit_group;");

    for (int kt = 0; kt < nkt; kt++) {
        int cur = kt & 1;
        if (kt + 1 < nkt) {
            load_stage(cur ^ 1, (kt + 1) * BKT);
            asm volatile("cp.async.commit_group;");
            asm volatile("cp.async.wait_group 1;");
        } else {
            asm volatile("cp.async.wait_group 0;");
        }
        __syncthreads();

        const uint32_t* As = (const uint32_t*)(sm + cur * STAGEF);
        const uint32_t* Bs = As + BMT * PADW;

#pragma unroll
        for (int ks = 0; ks < BKT; ks += 8) {
            uint32_t afr[4][4], bfr[4][2];
#pragma unroll
            for (int mi = 0; mi < 4; mi++) {
                int rb = wm * 64 + mi * 16;
                afr[mi][0] = As[(rb + g    ) * PADW + ks + tg    ];
                afr[mi][1] = As[(rb + g + 8) * PADW + ks + tg    ];
                afr[mi][2] = As[(rb + g    ) * PADW + ks + tg + 4];
                afr[mi][3] = As[(rb + g + 8) * PADW + ks + tg + 4];
            }
#pragma unroll
            for (int ni = 0; ni < 4; ni++) {
                int nb = wn * 32 + ni * 8;
                bfr[ni][0] = Bs[(nb + g) * PADW + ks + tg    ];
                bfr[ni][1] = Bs[(nb + g) * PADW + ks + tg + 4];
            }
#pragma unroll
            for (int mi = 0; mi < 4; mi++)
#pragma unroll
                for (int ni = 0; ni < 4; ni++)
                    MMA_TF32(acc[mi][ni], afr[mi][0], afr[mi][1], afr[mi][2], afr[mi][3],
                             bfr[ni][0], bfr[ni][1]);
        }
        __syncthreads();
    }

#pragma unroll
    for (int mi = 0; mi < 4; mi++) {
        int row = m0 + wm * 64 + mi * 16 + g;
#pragma unroll
        for (int ni = 0; ni < 4; ni++) {
            int col = n0 + wn * 32 + ni * 8 + 2 * tg;
            *(float2*)&C[(size_t)row * N + col] =
                make_float2(acc[mi][ni][0], acc[mi][ni][1]);
            *(float2*)&C[(size_t)(row + 8) * N + col] =
                make_float2(acc[mi][ni][2], acc[mi][ni][3]);
        }
    }
}

// ---------------------------------------------------------------------------
// Fused RMSNorm + RoPE (in place). One warp per (token, head).
// ---------------------------------------------------------------------------
__global__ void norm_rope_kernel(float* __restrict__ buf,
                                 const float* __restrict__ w,
                                 const float* __restrict__ cosb,
                                 const float* __restrict__ sinb,
                                 int H, int total_rows)
{
    int gw = (blockIdx.x * blockDim.x + threadIdx.x) >> 5;
    if (gw >= total_rows) return;
    int lane = threadIdx.x & 31;
    int h   = gw % H;
    int tok = gw / H;
    int tpos = tok & (TT - 1);
    float* row = buf + (size_t)tok * H * HD + (size_t)h * HD;

    float2 v0 = *(float2*)&row[2 * lane];
    float2 v1 = make_float2(0.f, 0.f);
    if (lane < 16) v1 = *(float2*)&row[2 * (lane + 32)];

    float ss = v0.x*v0.x + v0.y*v0.y + v1.x*v1.x + v1.y*v1.y;
#pragma unroll
    for (int off = 16; off; off >>= 1)
        ss += __shfl_xor_sync(0xffffffffu, ss, off);
    float inv = 1.0f / sqrtf(ss * (1.0f / HD) + 1e-6f);

    const float* cr = cosb + (size_t)tpos * HD;
    const float* sr = sinb + (size_t)tpos * HD;
    {
        int i2 = 2 * lane;
        float xr = w[i2] * v0.x * inv;
        float xi = w[i2 + 1] * v0.y * inv;
        float o0 = xr * cr[i2]     - xi * sr[i2];
        float o1 = xr * sr[i2 + 1] + xi * cr[i2 + 1];
        *(float2*)&row[i2] = make_float2(o0, o1);
    }
    if (lane < 16) {
        int i2 = 2 * (lane + 32);
        float xr = w[i2] * v1.x * inv;
        float xi = w[i2 + 1] * v1.y * inv;
        float o0 = xr * cr[i2]     - xi * sr[i2];
        float o1 = xr * sr[i2 + 1] + xi * cr[i2 + 1];
        *(float2*)&row[i2] = make_float2(o0, o1);
    }
}

// ---------------------------------------------------------------------------
// Tensor-core flash attention (TF32), FlashAttention-2 style.
// Block = (128 q-rows, head, batch). 8 warps x 16 q-rows each.
// KV tiles of 64 rows double-buffered via cp.async.
// K/V smem layout [64][100]; P per-warp [16][68].
// Inputs q (unrounded; rounded here after scaling), k/v pre-rounded to tf32.
// Output rounded to tf32 for the wo GEMM.
// ---------------------------------------------------------------------------
#define AKV_STAGEF 12800                   // (64*100)*2 matrices per stage
#define ATTN_SMEM_FLOATS (2*AKV_STAGEF + 8*16*68)
#define ATTN_SMEM_BYTES  (ATTN_SMEM_FLOATS*4)

__global__ __launch_bounds__(256, 1)
void attn_tc_kernel(const float* __restrict__ q, const float* __restrict__ k,
                    const float* __restrict__ v, float* __restrict__ o)
{
    extern __shared__ float sm[];
    const int tid  = threadIdx.x;
    const int warp = tid >> 5;
    const int lane = tid & 31;
    const int g    = lane >> 2;
    const int tg   = lane & 3;

    const int qt = blockIdx.x;
    const int h  = blockIdx.y;
    const int b  = blockIdx.z;
    const int kvh = h >> 2;
    const int q0 = qt * 128;
    const int row0 = warp * 16;

    const float* qb = q + (size_t)b * TT * QDIM  + (size_t)h   * HD;
    const float* kb = k + (size_t)b * TT * KVDIM + (size_t)kvh * HD;
    const float* vb = v + (size_t)b * TT * KVDIM + (size_t)kvh * HD;
    float*       ob = o + (size_t)b * TT * QDIM  + (size_t)h   * HD;

    float* Ps = sm + 2 * AKV_STAGEF + warp * (16 * 68);

    // --- Load Q fragments (16 rows x 96), pre-scaled & tf32-rounded ---
    uint32_t qf[12][4];
    {
        const float scale = 0.1020620726159658f;  // 1/sqrt(96)
        const float* r0p = qb + (size_t)(q0 + row0 + g)     * QDIM;
        const float* r8p = qb + (size_t)(q0 + row0 + g + 8) * QDIM;
#pragma unroll
        for (int ks = 0; ks < 12; ks++) {
            int k0 = ks * 8;
            qf[ks][0] = f2tf32u(r0p[k0 + tg]     * scale);
            qf[ks][1] = f2tf32u(r8p[k0 + tg]     * scale);
            qf[ks][2] = f2tf32u(r0p[k0 + tg + 4] * scale);
            qf[ks][3] = f2tf32u(r8p[k0 + tg + 4] * scale);
        }
    }

    float oacc[12][4];
#pragma unroll
    for (int i = 0; i < 12; i++)
#pragma unroll
        for (int j = 0; j < 4; j++) oacc[i][j] = 0.f;

    float m0 = -1e30f, m1 = -1e30f, l0 = 0.f, l1 = 0.f;

    const int nt = 2 * qt + 2;   // kv tiles (64 rows each) under causal mask

    // KV stage loader: K -> dst[0..6400), V -> dst[6400..12800)
    auto load_kv = [&](int stage, int kt) {
        float* dst = sm + stage * AKV_STAGEF;
        const float* kbt = kb + (size_t)(kt * 64) * KVDIM;
        const float* vbt = vb + (size_t)(kt * 64) * KVDIM;
#pragma unroll
        for (int j = 0; j < 6; j++) {
            int c  = tid + j * 256;       // 0..1535
            int r  = c / 24;
            int c4 = (c % 24) * 4;
            uint32_t dk = (uint32_t)__cvta_generic_to_shared(&dst[r * 100 + c4]);
            asm volatile("cp.async.cg.shared.global [%0], [%1], 16;"
                         :: "r"(dk), "l"(kbt + (size_t)r * KVDIM + c4));
            uint32_t dv = (uint32_t)__cvta_generic_to_shared(&dst[6400 + r * 100 + c4]);
            asm volatile("cp.async.cg.shared.global [%0], [%1], 16;"
                         :: "r"(dv), "l"(vbt + (size_t)r * KVDIM + c4));
        }
    };

    load_kv(0, 0);
    asm volatile("cp.async.commit_group;");

    for (int kt = 0; kt < nt; kt++) {
        int cur = kt & 1;
        if (kt + 1 < nt) {
            load_kv(cur ^ 1, kt + 1);
            asm volatile("cp.async.commit_group;");
            asm volatile("cp.async.wait_group 1;");
        } else {
            asm volatile("cp.async.wait_group 0;");
        }
        __syncthreads();

        const float* Ks = sm + cur * AKV_STAGEF;
        const float* Vs = Ks + 6400;

        // --- S = Q K^T (16x64 per warp) ---
        float sacc[8][4];
#pragma unroll
        for (int i = 0; i < 8; i++)
#pragma unroll
            for (int j = 0; j < 4; j++) sacc[i][j] = 0.f;

#pragma unroll
        for (int ks = 0; ks < 12; ks++) {
            int k0 = ks * 8;
#pragma unroll
            for (int ni = 0; ni < 8; ni++) {
                uint32_t b0 = *(const uint32_t*)&Ks[(ni * 8 + g) * 100 + k0 + tg];
                uint32_t b1 = *(const uint32_t*)&Ks[(ni * 8 + g) * 100 + k0 + tg + 4];
                MMA_TF32(sacc[ni], qf[ks][0], qf[ks][1], qf[ks][2], qf[ks][3], b0, b1);
            }
        }

        // --- Causal mask (only diagonal-overlapping tiles) ---
        const int rg = q0 + row0 + g;
        const int r8 = rg + 8;
        if (kt >= 2 * qt) {
#pragma unroll
            for (int ni = 0; ni < 8; ni++) {
                int kbase = kt * 64 + ni * 8 + 2 * tg;
                if (kbase     > rg) sacc[ni][0] = -1e30f;
                if (kbase + 1 > rg) sacc[ni][1] = -1e30f;
                if (kbase     > r8) sacc[ni][2] = -1e30f;
                if (kbase + 1 > r8) sacc[ni][3] = -1e30f;
            }
        }

        // --- Online softmax (rows g and g+8) ---
        float mx0 = -1e30f, mx1 = -1e30f;
#pragma unroll
        for (int ni = 0; ni < 8; ni++) {
            mx0 = fmaxf(mx0, fmaxf(sacc[ni][0], sacc[ni][1]));
            mx1 = fmaxf(mx1, fmaxf(sacc[ni][2], sacc[ni][3]));
        }
        mx0 = fmaxf(mx0, __shfl_xor_sync(0xffffffffu, mx0, 1));
        mx0 = fmaxf(mx0, __shfl_xor_sync(0xffffffffu, mx0, 2));
        mx1 = fmaxf(mx1, __shfl_xor_sync(0xffffffffu, mx1, 1));
        mx1 = fmaxf(mx1, __shfl_xor_sync(0xffffffffu, mx1, 2));

        float mn0 = fmaxf(m0, mx0), mn1 = fmaxf(m1, mx1);
        float a0 = __expf(m0 - mn0), a1 = __expf(m1 - mn1);
        float s0 = 0.f, s1 = 0.f;
#pragma unroll
        for (int ni = 0; ni < 8; ni++) {
            float p0 = __expf(sacc[ni][0] - mn0);
            float p1 = __expf(sacc[ni][1] - mn0);
            float p2 = __expf(sacc[ni][2] - mn1);
            float p3 = __expf(sacc[ni][3] - mn1);
            sacc[ni][0] = p0; sacc[ni][1] = p1;
            sacc[ni][2] = p2; sacc[ni][3] = p3;
            s0 += p0 + p1; s1 += p2 + p3;
        }
        s0 += __shfl_xor_sync(0xffffffffu, s0, 1);
        s0 += __shfl_xor_sync(0xffffffffu, s0, 2);
        s1 += __shfl_xor_sync(0xffffffffu, s1, 1);
        s1 += __shfl_xor_sync(0xffffffffu, s1, 2);
        l0 = l0 * a0 + s0; l1 = l1 * a1 + s1;
        m0 = mn0; m1 = mn1;

#pragma unroll
        for (int nn = 0; nn < 12; nn++) {
            oacc[nn][0] *= a0; oacc[nn][1] *= a0;
            oacc[nn][2] *= a1; oacc[nn][3] *= a1;
        }

        // --- P -> per-warp smem (tf32-rounded) ---
        __syncwarp();
#pragma unroll
        for (int ni = 0; ni < 8; ni++) {
            int cb = ni * 8 + 2 * tg;
            *(float2*)&Ps[g * 68 + cb] =
                make_float2(f2tf32f(sacc[ni][0]), f2tf32f(sacc[ni][1]));
            *(float2*)&Ps[(g + 8) * 68 + cb] =
                make_float2(f2tf32f(sacc[ni][2]), f2tf32f(sacc[ni][3]));
        }
        __syncwarp();

        // --- O += P V (16x96 per warp) ---
#pragma unroll
        for (int kk = 0; kk < 8; kk++) {
            int k0 = kk * 8;
            uint32_t af0 = *(const uint32_t*)&Ps[g * 68 + k0 + tg];
            uint32_t af1 = *(const uint32_t*)&Ps[(g + 8) * 68 + k0 + tg];
            uint32_t af2 = *(const uint32_t*)&Ps[g * 68 + k0 + tg + 4];
            uint32_t af3 = *(const uint32_t*)&Ps[(g + 8) * 68 + k0 + tg + 4];
#pragma unroll
            for (int nn = 0; nn < 12; nn++) {
                uint32_t b0 = *(const uint32_t*)&Vs[(k0 + tg)     * 100 + nn * 8 + g];
                uint32_t b1 = *(const uint32_t*)&Vs[(k0 + tg + 4) * 100 + nn * 8 + g];
                MMA_TF32(oacc[nn], af0, af1, af2, af3, b0, b1);
            }
        }
        __syncthreads();   // protect KV stage reuse by next iteration's cp.async
    }

    // --- Epilogue: normalize, round to tf32, store ---
    float i0 = 1.f / l0, i1 = 1.f / l1;
    float* o0 = ob + (size_t)(q0 + row0 + g)     * QDIM;
    float* o8 = ob + (size_t)(q0 + row0 + g + 8) * QDIM;
#pragma unroll
    for (int nn = 0; nn < 12; nn++) {
        int col = nn * 8 + 2 * tg;
        *(float2*)&o0[col] = make_float2(f2tf32f(oacc[nn][0] * i0),
                                         f2tf32f(oacc[nn][1] * i0));
        *(float2*)&o8[col] = make_float2(f2tf32f(oacc[nn][2] * i1),
                                         f2tf32f(oacc[nn][3] * i1));
    }
}

// ---------------------------------------------------------------------------
// Launch
// ---------------------------------------------------------------------------
extern "C" void kernel_launch(void* const* d_in, const int* in_sizes, int n_in,
                              void* d_out, int out_size)
{
    const float* x    = (const float*)d_in[0];
    const float* wq   = (const float*)d_in[2];
    const float* wk   = (const float*)d_in[3];
    const float* wv   = (const float*)d_in[4];
    const float* wo   = (const float*)d_in[5];
    const float* qnw  = (const float*)d_in[6];
    const float* knw  = (const float*)d_in[7];
    const float* cosb = (const float*)d_in[8];
    const float* sinb = (const float*)d_in[9];
    float* out = (float*)d_out;

    void *pq, *pk, *pv, *pa, *pxr, *pwq, *pwk, *pwv, *pwo;
    cudaGetSymbolAddress(&pq, g_q);
    cudaGetSymbolAddress(&pk, g_k);
    cudaGetSymbolAddress(&pv, g_v);
    cudaGetSymbolAddress(&pa, g_attn);
    cudaGetSymbolAddress(&pxr, g_xr);
    cudaGetSymbolAddress(&pwq, g_wqr);
    cudaGetSymbolAddress(&pwk, g_wkr);
    cudaGetSymbolAddress(&pwv, g_wvr);
    cudaGetSymbolAddress(&pwo, g_wor);
    float* fq = (float*)pq;   float* fk = (float*)pk;
    float* fv = (float*)pv;   float* fa = (float*)pa;
    float* fxr = (float*)pxr; float* fwq = (float*)pwq;
    float* fwk = (float*)pwk; float* fwv = (float*)pwv;
    float* fwo = (float*)pwo;

    cudaFuncSetAttribute(attn_tc_kernel, cudaFuncAttributeMaxDynamicSharedMemorySize,
                         ATTN_SMEM_BYTES);
    cudaFuncSetAttribute(tf32_gemm_db, cudaFuncAttributeMaxDynamicSharedMemorySize,
                         GEMM_SMEM_BYTES);

    dim3 blk(256);

    // tf32 rounding pre-passes (x + weights)
    {
        int n;
        n = NTOK * DMODEL / 4;  tf32_round_kernel<<<(n+255)/256, blk>>>(x,  fxr, n);
        n = QDIM * DMODEL / 4;  tf32_round_kernel<<<(n+255)/256, blk>>>(wq, fwq, n);
        n = KVDIM * DMODEL / 4; tf32_round_kernel<<<(n+255)/256, blk>>>(wk, fwk, n);
        n = KVDIM * DMODEL / 4; tf32_round_kernel<<<(n+255)/256, blk>>>(wv, fwv, n);
        n = DMODEL * QDIM / 4;  tf32_round_kernel<<<(n+255)/256, blk>>>(wo, fwo, n);
    }

    // QKV projections (TF32 tensor cores, double-buffered)
    tf32_gemm_db<<<dim3(QDIM / 128,  NTOK / 128), blk, GEMM_SMEM_BYTES>>>(fxr, fwq, fq, NTOK, QDIM,  DMODEL);
    tf32_gemm_db<<<dim3(KVDIM / 128, NTOK / 128), blk, GEMM_SMEM_BYTES>>>(fxr, fwk, fk, NTOK, KVDIM, DMODEL);
    tf32_gemm_db<<<dim3(KVDIM / 128, NTOK / 128), blk, GEMM_SMEM_BYTES>>>(fxr, fwv, fv, NTOK, KVDIM, DMODEL);

    // RMSNorm + RoPE on q and k
    {
        int rows_q = NTOK * NHEADS;
        int rows_k = NTOK * NKV;
        norm_rope_kernel<<<(rows_q * 32 + 255) / 256, blk>>>(fq, qnw, cosb, sinb, NHEADS, rows_q);
        norm_rope_kernel<<<(rows_k * 32 + 255) / 256, blk>>>(fk, knw, cosb, sinb, NKV, rows_k);
    }

    // Round K and V to tf32 for the attention MMAs (Q rounded in-kernel after scaling)
    {
        int n = NTOK * KVDIM / 4;
        tf32_round_kernel<<<(n+255)/256, blk>>>(fk, fk, n);
        tf32_round_kernel<<<(n+255)/256, blk>>>(fv, fv, n);
    }

    // Attention (TF32 tensor cores)
    attn_tc_kernel<<<dim3(TT / 128, NHEADS, BB), blk, ATTN_SMEM_BYTES>>>(fq, fk, fv, fa);

    // Output projection (TF32 tensor cores, double-buffered)
    tf32_gemm_db<<<dim3(DMODEL / 128, NTOK / 128), blk, GEMM_SMEM_BYTES>>>(fa, fwo, out, NTOK, DMODEL, DMODEL);
}

// round 6
// speedup vs baseline: 14.2308x; 2.2569x over previous
#include <cuda_runtime.h>
#include <cuda_fp16.h>
#include <math.h>
#include <stdint.h>

// Problem constants
#define BB 2
#define TT 1024
#define DMODEL 3072
#define NHEADS 32
#define NKV 8
#define HD 96
#define NTOK 2048
#define QDIM 3072
#define KVDIM 768
#define QKVN 4608            // fused projection width (q|k|v)
#define QKH  3840            // half buffer stride (q|k only)

// Scratch (static device globals; no allocation allowed)
__device__ float  g_qkv[(size_t)NTOK*QKVN];      // fp32 fused QKV GEMM output
__device__ __half g_xh[(size_t)NTOK*DMODEL];
__device__ __half g_wh[(size_t)QKVN*DMODEL];     // [wq;wk;wv] fp16
__device__ __half g_woh[(size_t)DMODEL*QDIM];
__device__ __half g_qkvh[(size_t)NTOK*QKH];      // q(scaled)|k in fp16
__device__ __half g_vT[(size_t)BB*NKV*HD*TT];    // V transposed: [b*kvh][dim][tok]
__device__ __half g_attnh[(size_t)NTOK*QDIM];    // attention output fp16

// ---------------------------------------------------------------------------
// Helpers
// ---------------------------------------------------------------------------
__device__ __forceinline__ uint32_t smem_u32(const void* p) {
    uint32_t a;
    asm("{ .reg .u64 t; cvta.to.shared.u64 t, %1; cvt.u32.u64 %0, t; }"
        : "=r"(a) : "l"(p));
    return a;
}

#define MMA_F16(acc, a, b)                                                    \
    asm volatile(                                                             \
        "mma.sync.aligned.m16n8k16.row.col.f32.f16.f16.f32 "                  \
        "{%0,%1,%2,%3}, {%4,%5,%6,%7}, {%8,%9}, {%0,%1,%2,%3};"               \
        : "+f"((acc)[0]), "+f"((acc)[1]), "+f"((acc)[2]), "+f"((acc)[3])      \
        : "r"((a)[0]), "r"((a)[1]), "r"((a)[2]), "r"((a)[3]),                 \
          "r"((b)[0]), "r"((b)[1]))

#define LDSM_X4(r, addr)                                                      \
    asm volatile("ldmatrix.sync.aligned.m8n8.x4.shared.b16 {%0,%1,%2,%3}, [%4];" \
        : "=r"((r)[0]), "=r"((r)[1]), "=r"((r)[2]), "=r"((r)[3]) : "r"(addr))

#define LDSM_X2(r, addr)                                                      \
    asm volatile("ldmatrix.sync.aligned.m8n8.x2.shared.b16 {%0,%1}, [%2];"    \
        : "=r"((r)[0]), "=r"((r)[1]) : "r"(addr))

#define CP_ASYNC16(dst, src)                                                  \
    asm volatile("cp.async.cg.shared.global [%0], [%1], 16;" :: "r"(dst), "l"(src))

// ---------------------------------------------------------------------------
// fp32 -> fp16 conversion (contiguous, vectorized)
// ---------------------------------------------------------------------------
__global__ void f2h_kernel(const float* __restrict__ in,
                           __half* __restrict__ out, int n4)
{
    int i = blockIdx.x * blockDim.x + threadIdx.x;
    if (i >= n4) return;
    float4 v = ((const float4*)in)[i];
    ((__half2*)out)[2*i]   = __floats2half2_rn(v.x, v.y);
    ((__half2*)out)[2*i+1] = __floats2half2_rn(v.z, v.w);
}

// ---------------------------------------------------------------------------
// fp16 tensor-core GEMM: C[M,N](fp32) = A[M,K] * B[N,K]^T, A/B fp16.
// Block 128x128, K-tile 64, 8 warps (2x4), warp 64x32, mma m16n8k16,
// ldmatrix fragment loads, cp.async double buffer.
// Requires M%128==0, N%128==0, K%64==0.
// ---------------------------------------------------------------------------
#define HPITCH  72                    // halves per smem row
#define HPITCHB 144                   // bytes (16B-aligned: 16*9)
#define HSTG    (128 * HPITCHB)       // 18432 per matrix
#define HSTAGE  (2 * HSTG)            // 36864 per stage (A+B)
#define HGEMM_SMEM (2 * HSTAGE)       // 73728

__global__ __launch_bounds__(256)
void gemm_h(const __half* __restrict__ A, const __half* __restrict__ B,
            float* __restrict__ C, int M, int N, int K)
{
    extern __shared__ char smem[];
    const uint32_t sbase = smem_u32(smem);
    const int tid  = threadIdx.x;
    const int warp = tid >> 5;
    const int lane = tid & 31;
    const int g  = lane >> 2;
    const int tg = lane & 3;
    const int wm = warp & 1;
    const int wn = warp >> 1;
    const int m0 = blockIdx.y * 128;
    const int n0 = blockIdx.x * 128;

    float acc[4][4][4];
#pragma unroll
    for (int i = 0; i < 4; i++)
#pragma unroll
        for (int j = 0; j < 4; j++)
#pragma unroll
            for (int r = 0; r < 4; r++) acc[i][j][r] = 0.f;

    // ldmatrix per-lane byte offsets within a tile
    const uint32_t aoff = ((lane & 15) * HPITCH + (lane >> 4) * 8) * 2;
    const uint32_t boff = ((lane & 7) * HPITCH + ((lane >> 3) & 1) * 8) * 2;

    const int lr = tid >> 3;          // staging row within 128-row pass? (tid/8: 0..31)
    const int lc = tid & 7;           // chunk within row

    auto load_stage = [&](int s, int k0) {
        const uint32_t stg = sbase + s * HSTAGE;
#pragma unroll
        for (int i = 0; i < 4; i++) {
            int r = lr + i * 32;
            uint32_t da = stg + r * HPITCHB + lc * 16;
            CP_ASYNC16(da, A + (size_t)(m0 + r) * K + k0 + lc * 8);
            uint32_t db = stg + HSTG + r * HPITCHB + lc * 16;
            CP_ASYNC16(db, B + (size_t)(n0 + r) * K + k0 + lc * 8);
        }
    };

    const int nkt = K / 64;

    load_stage(0, 0);
    asm volatile("cp.async.commit_group;");

    for (int kt = 0; kt < nkt; kt++) {
        int cur = kt & 1;
        if (kt + 1 < nkt) {
            load_stage(cur ^ 1, (kt + 1) * 64);
            asm volatile("cp.async.commit_group;");
            asm volatile("cp.async.wait_group 1;");
        } else {
            asm volatile("cp.async.wait_group 0;");
        }
        __syncthreads();

        const uint32_t stgA = sbase + cur * HSTAGE + wm * 64 * HPITCHB + aoff;
        const uint32_t stgB = sbase + cur * HSTAGE + HSTG + wn * 32 * HPITCHB + boff;

#pragma unroll
        for (int ks = 0; ks < 4; ks++) {
            uint32_t af[4][4], bf[4][2];
#pragma unroll
            for (int mi = 0; mi < 4; mi++)
                LDSM_X4(af[mi], stgA + mi * 16 * HPITCHB + ks * 32);
#pragma unroll
            for (int ni = 0; ni < 4; ni++)
                LDSM_X2(bf[ni], stgB + ni * 8 * HPITCHB + ks * 32);
#pragma unroll
            for (int mi = 0; mi < 4; mi++)
#pragma unroll
                for (int ni = 0; ni < 4; ni++)
                    MMA_F16(acc[mi][ni], af[mi], bf[ni]);
        }
        __syncthreads();
    }

#pragma unroll
    for (int mi = 0; mi < 4; mi++) {
        int row = m0 + wm * 64 + mi * 16 + g;
#pragma unroll
        for (int ni = 0; ni < 4; ni++) {
            int col = n0 + wn * 32 + ni * 8 + 2 * tg;
            *(float2*)&C[(size_t)row * N + col] =
                make_float2(acc[mi][ni][0], acc[mi][ni][1]);
            *(float2*)&C[(size_t)(row + 8) * N + col] =
                make_float2(acc[mi][ni][2], acc[mi][ni][3]);
        }
    }
}

// ---------------------------------------------------------------------------
// Fused RMSNorm + RoPE, fp32 in -> fp16 out (optionally scaled).
// One warp per (token, head).
// ---------------------------------------------------------------------------
__global__ void norm_rope_h_kernel(const float* __restrict__ src,
                                   __half* __restrict__ dst,
                                   const float* __restrict__ w,
                                   const float* __restrict__ cosb,
                                   const float* __restrict__ sinb,
                                   int H, int total_rows,
                                   int ld_src, int ld_dst, float outscale)
{
    int gw = (blockIdx.x * blockDim.x + threadIdx.x) >> 5;
    if (gw >= total_rows) return;
    int lane = threadIdx.x & 31;
    int h   = gw % H;
    int tok = gw / H;
    int tpos = tok & (TT - 1);
    const float* row = src + (size_t)tok * ld_src + (size_t)h * HD;
    __half*      dro = dst + (size_t)tok * ld_dst + (size_t)h * HD;

    float2 v0 = *(const float2*)&row[2 * lane];
    float2 v1 = make_float2(0.f, 0.f);
    if (lane < 16) v1 = *(const float2*)&row[2 * (lane + 32)];

    float ss = v0.x*v0.x + v0.y*v0.y + v1.x*v1.x + v1.y*v1.y;
#pragma unroll
    for (int off = 16; off; off >>= 1)
        ss += __shfl_xor_sync(0xffffffffu, ss, off);
    float inv = outscale / sqrtf(ss * (1.0f / HD) + 1e-6f);

    const float* cr = cosb + (size_t)tpos * HD;
    const float* sr = sinb + (size_t)tpos * HD;
    {
        int i2 = 2 * lane;
        float xr = w[i2] * v0.x * inv;
        float xi = w[i2 + 1] * v0.y * inv;
        float o0 = xr * cr[i2]     - xi * sr[i2];
        float o1 = xr * sr[i2 + 1] + xi * cr[i2 + 1];
        *(__half2*)&dro[i2] = __floats2half2_rn(o0, o1);
    }
    if (lane < 16) {
        int i2 = 2 * (lane + 32);
        float xr = w[i2] * v1.x * inv;
        float xi = w[i2 + 1] * v1.y * inv;
        float o0 = xr * cr[i2]     - xi * sr[i2];
        float o1 = xr * sr[i2 + 1] + xi * cr[i2 + 1];
        *(__half2*)&dro[i2] = __floats2half2_rn(o0, o1);
    }
}

// ---------------------------------------------------------------------------
// V transpose + fp16 convert: g_qkv v-block -> g_vT[b*kvh][dim][tok]
// grid (16 heads, 16 tok-blocks of 64, 3 dim-blocks of 32), block 256.
// ---------------------------------------------------------------------------
__global__ void v_transpose_kernel(const float* __restrict__ qkv,
                                   __half* __restrict__ vT)
{
    __shared__ __half tile[32 * 66];
    const int headi = blockIdx.x;           // b*NKV + kvh
    const int t0 = blockIdx.y * 64;
    const int d0 = blockIdx.z * 32;
    const int b   = headi >> 3;
    const int kvh = headi & 7;
    const float* src = qkv + (size_t)b * TT * QKVN + QKH + (size_t)kvh * HD;

#pragma unroll
    for (int i = 0; i < 8; i++) {
        int idx = threadIdx.x + i * 256;
        int tr = idx >> 5, dc = idx & 31;
        float v = src[(size_t)(t0 + tr) * QKVN + d0 + dc];
        tile[dc * 66 + tr] = __float2half_rn(v);
    }
    __syncthreads();

    __half* dst = vT + (size_t)headi * HD * TT;
#pragma unroll
    for (int i = 0; i < 8; i++) {
        int idx = threadIdx.x + i * 256;
        int dr = idx >> 6, tc = idx & 63;
        dst[(size_t)(d0 + dr) * TT + t0 + tc] = tile[dr * 66 + tc];
    }
}

// ---------------------------------------------------------------------------
// fp16 tensor-core flash attention (FlashAttention-2 style).
// Block = (128 q-rows, head, batch), 8 warps x 16 rows.
// K smem [64][104 halves]; V^T smem [96][72 halves]; P per-warp [16][72 halves].
// q pre-scaled fp16 (stride 3840), k fp16 (stride 3840), vT fp16.
// Output fp16 (stride 3072).
// ---------------------------------------------------------------------------
#define KP   52                        // K smem pitch (uint32 units; 104 halves)
#define VP   36                        // VT smem pitch (uint32; 72 halves)
#define K_STG_B   (64 * 104 * 2)       // 13312
#define VT_STG_B  (96 * 72 * 2)        // 13824
#define AKV_STG_B (K_STG_B + VT_STG_B) // 27136
#define PP   36                        // P pitch (uint32; 72 halves)
#define ATTN_SMEM_B (2 * AKV_STG_B + 8 * 16 * PP * 4)   // 72704

__global__ __launch_bounds__(256, 1)
void attn_h_kernel(const __half* __restrict__ qk, const __half* __restrict__ vT,
                   __half* __restrict__ o)
{
    extern __shared__ char smem[];
    const int tid  = threadIdx.x;
    const int warp = tid >> 5;
    const int lane = tid & 31;
    const int g    = lane >> 2;
    const int tg   = lane & 3;

    const int qt = blockIdx.x;
    const int h  = blockIdx.y;
    const int b  = blockIdx.z;
    const int kvh = h >> 2;
    const int q0 = qt * 128;
    const int row0 = warp * 16;

    const __half* qb  = qk + (size_t)b * TT * QKH + (size_t)h * HD;
    const __half* kb  = qk + (size_t)b * TT * QKH + QDIM + (size_t)kvh * HD;
    const __half* vTb = vT + (size_t)(b * NKV + kvh) * HD * TT;
    __half*       ob  = o  + (size_t)b * TT * QDIM + (size_t)h * HD;

    uint32_t* Psu = (uint32_t*)(smem + 2 * AKV_STG_B) + warp * 16 * PP;

    // --- Q fragments (pre-scaled fp16 in global) ---
    uint32_t qf[6][4];
    {
        const __half* r0p = qb + (size_t)(q0 + row0 + g)     * QKH;
        const __half* r8p = qb + (size_t)(q0 + row0 + g + 8) * QKH;
#pragma unroll
        for (int ks = 0; ks < 6; ks++) {
            qf[ks][0] = *(const uint32_t*)&r0p[ks * 16 + 2 * tg];
            qf[ks][1] = *(const uint32_t*)&r8p[ks * 16 + 2 * tg];
            qf[ks][2] = *(const uint32_t*)&r0p[ks * 16 + 2 * tg + 8];
            qf[ks][3] = *(const uint32_t*)&r8p[ks * 16 + 2 * tg + 8];
        }
    }

    float oacc[12][4];
#pragma unroll
    for (int i = 0; i < 12; i++)
#pragma unroll
        for (int j = 0; j < 4; j++) oacc[i][j] = 0.f;

    float m0 = -1e30f, m1 = -1e30f, l0 = 0.f, l1 = 0.f;
    const int nt = 2 * qt + 2;

    // Stage loader: K (64 rows x 12 chunks) + VT (96 rows x 8 chunks)
    auto load_kv = [&](int stage, int kt) {
        const uint32_t stg = smem_u32(smem) + stage * AKV_STG_B;
#pragma unroll
        for (int j = 0; j < 6; j++) {
            int c = tid + j * 256;
            if (c < 768) {
                int r = c / 12, cc = c % 12;
                uint32_t dst = stg + r * 208 + cc * 16;
                CP_ASYNC16(dst, kb + (size_t)(kt * 64 + r) * QKH + cc * 8);
            } else {
                int c2 = c - 768;
                int r = c2 >> 3, cc = c2 & 7;
                uint32_t dst = stg + K_STG_B + r * 144 + cc * 16;
                CP_ASYNC16(dst, vTb + (size_t)r * TT + kt * 64 + cc * 8);
            }
        }
    };

    load_kv(0, 0);
    asm volatile("cp.async.commit_group;");

    for (int kt = 0; kt < nt; kt++) {
        int cur = kt & 1;
        if (kt + 1 < nt) {
            load_kv(cur ^ 1, kt + 1);
            asm volatile("cp.async.commit_group;");
            asm volatile("cp.async.wait_group 1;");
        } else {
            asm volatile("cp.async.wait_group 0;");
        }
        __syncthreads();

        const uint32_t* Ksu = (const uint32_t*)(smem + cur * AKV_STG_B);
        const uint32_t* VTu = (const uint32_t*)(smem + cur * AKV_STG_B + K_STG_B);

        // --- S = Q K^T (16x64 per warp) ---
        float sacc[8][4];
#pragma unroll
        for (int i = 0; i < 8; i++)
#pragma unroll
            for (int j = 0; j < 4; j++) sacc[i][j] = 0.f;

#pragma unroll
        for (int ks = 0; ks < 6; ks++) {
#pragma unroll
            for (int ni = 0; ni < 8; ni++) {
                uint32_t bf[2];
                bf[0] = Ksu[(ni * 8 + g) * KP + ks * 8 + tg];
                bf[1] = Ksu[(ni * 8 + g) * KP + ks * 8 + tg + 4];
                MMA_F16(sacc[ni], qf[ks], bf);
            }
        }

        // --- Causal mask ---
        const int rg = q0 + row0 + g;
        const int r8 = rg + 8;
        if (kt >= 2 * qt) {
#pragma unroll
            for (int ni = 0; ni < 8; ni++) {
                int kbase = kt * 64 + ni * 8 + 2 * tg;
                if (kbase     > rg) sacc[ni][0] = -1e30f;
                if (kbase + 1 > rg) sacc[ni][1] = -1e30f;
                if (kbase     > r8) sacc[ni][2] = -1e30f;
                if (kbase + 1 > r8) sacc[ni][3] = -1e30f;
            }
        }

        // --- Online softmax (rows g, g+8) ---
        float mx0 = -1e30f, mx1 = -1e30f;
#pragma unroll
        for (int ni = 0; ni < 8; ni++) {
            mx0 = fmaxf(mx0, fmaxf(sacc[ni][0], sacc[ni][1]));
            mx1 = fmaxf(mx1, fmaxf(sacc[ni][2], sacc[ni][3]));
        }
        mx0 = fmaxf(mx0, __shfl_xor_sync(0xffffffffu, mx0, 1));
        mx0 = fmaxf(mx0, __shfl_xor_sync(0xffffffffu, mx0, 2));
        mx1 = fmaxf(mx1, __shfl_xor_sync(0xffffffffu, mx1, 1));
        mx1 = fmaxf(mx1, __shfl_xor_sync(0xffffffffu, mx1, 2));

        float mn0 = fmaxf(m0, mx0), mn1 = fmaxf(m1, mx1);
        float a0 = __expf(m0 - mn0), a1 = __expf(m1 - mn1);
        float s0 = 0.f, s1 = 0.f;
#pragma unroll
        for (int ni = 0; ni < 8; ni++) {
            float p0 = __expf(sacc[ni][0] - mn0);
            float p1 = __expf(sacc[ni][1] - mn0);
            float p2 = __expf(sacc[ni][2] - mn1);
            float p3 = __expf(sacc[ni][3] - mn1);
            sacc[ni][0] = p0; sacc[ni][1] = p1;
            sacc[ni][2] = p2; sacc[ni][3] = p3;
            s0 += p0 + p1; s1 += p2 + p3;
        }
        s0 += __shfl_xor_sync(0xffffffffu, s0, 1);
        s0 += __shfl_xor_sync(0xffffffffu, s0, 2);
        s1 += __shfl_xor_sync(0xffffffffu, s1, 1);
        s1 += __shfl_xor_sync(0xffffffffu, s1, 2);
        l0 = l0 * a0 + s0; l1 = l1 * a1 + s1;
        m0 = mn0; m1 = mn1;

#pragma unroll
        for (int nn = 0; nn < 12; nn++) {
            oacc[nn][0] *= a0; oacc[nn][1] *= a0;
            oacc[nn][2] *= a1; oacc[nn][3] *= a1;
        }

        // --- P -> per-warp smem (fp16) ---
        __syncwarp();
#pragma unroll
        for (int ni = 0; ni < 8; ni++) {
            __half2 h0 = __floats2half2_rn(sacc[ni][0], sacc[ni][1]);
            __half2 h1 = __floats2half2_rn(sacc[ni][2], sacc[ni][3]);
            Psu[g * PP + ni * 4 + tg]       = *(uint32_t*)&h0;
            Psu[(g + 8) * PP + ni * 4 + tg] = *(uint32_t*)&h1;
        }
        __syncwarp();

        // --- O += P V (V^T layout: B-fragment contiguous in k) ---
#pragma unroll
        for (int kk = 0; kk < 4; kk++) {
            uint32_t af[4];
            af[0] = Psu[g * PP + kk * 8 + tg];
            af[1] = Psu[(g + 8) * PP + kk * 8 + tg];
            af[2] = Psu[g * PP + kk * 8 + tg + 4];
            af[3] = Psu[(g + 8) * PP + kk * 8 + tg + 4];
#pragma unroll
            for (int nn = 0; nn < 12; nn++) {
                uint32_t bf[2];
                bf[0] = VTu[(nn * 8 + g) * VP + kk * 8 + tg];
                bf[1] = VTu[(nn * 8 + g) * VP + kk * 8 + tg + 4];
                MMA_F16(oacc[nn], af, bf);
            }
        }
        __syncthreads();   // protect KV stage reuse
    }

    // --- Epilogue: normalize, convert fp16, store ---
    float i0 = 1.f / l0, i1 = 1.f / l1;
    __half2* o0 = (__half2*)(ob + (size_t)(q0 + row0 + g)     * QDIM);
    __half2* o8 = (__half2*)(ob + (size_t)(q0 + row0 + g + 8) * QDIM);
#pragma unroll
    for (int nn = 0; nn < 12; nn++) {
        o0[nn * 4 + tg] = __floats2half2_rn(oacc[nn][0] * i0, oacc[nn][1] * i0);
        o8[nn * 4 + tg] = __floats2half2_rn(oacc[nn][2] * i1, oacc[nn][3] * i1);
    }
}

// ---------------------------------------------------------------------------
// Launch
// ---------------------------------------------------------------------------
extern "C" void kernel_launch(void* const* d_in, const int* in_sizes, int n_in,
                              void* d_out, int out_size)
{
    const float* x    = (const float*)d_in[0];
    const float* wq   = (const float*)d_in[2];
    const float* wk   = (const float*)d_in[3];
    const float* wv   = (const float*)d_in[4];
    const float* wo   = (const float*)d_in[5];
    const float* qnw  = (const float*)d_in[6];
    const float* knw  = (const float*)d_in[7];
    const float* cosb = (const float*)d_in[8];
    const float* sinb = (const float*)d_in[9];
    float* out = (float*)d_out;

    void *pqkv, *pxh, *pwh, *pwoh, *pqkvh, *pvT, *pah;
    cudaGetSymbolAddress(&pqkv,  g_qkv);
    cudaGetSymbolAddress(&pxh,   g_xh);
    cudaGetSymbolAddress(&pwh,   g_wh);
    cudaGetSymbolAddress(&pwoh,  g_woh);
    cudaGetSymbolAddress(&pqkvh, g_qkvh);
    cudaGetSymbolAddress(&pvT,   g_vT);
    cudaGetSymbolAddress(&pah,   g_attnh);
    float*  fqkv = (float*)pqkv;
    __half* hx   = (__half*)pxh;
    __half* hw   = (__half*)pwh;
    __half* hwo  = (__half*)pwoh;
    __half* hqk  = (__half*)pqkvh;
    __half* hvT  = (__half*)pvT;
    __half* ha   = (__half*)pah;

    cudaFuncSetAttribute(gemm_h, cudaFuncAttributeMaxDynamicSharedMemorySize,
                         HGEMM_SMEM);
    cudaFuncSetAttribute(attn_h_kernel, cudaFuncAttributeMaxDynamicSharedMemorySize,
                         ATTN_SMEM_B);

    dim3 blk(256);

    // fp16 conversion pre-passes
    {
        int n;
        n = NTOK * DMODEL / 4;  f2h_kernel<<<(n+255)/256, blk>>>(x,  hx, n);
        n = QDIM * DMODEL / 4;  f2h_kernel<<<(n+255)/256, blk>>>(wq, hw, n);
        n = KVDIM * DMODEL / 4; f2h_kernel<<<(n+255)/256, blk>>>(
                                    wk, hw + (size_t)QDIM * DMODEL, n);
        n = KVDIM * DMODEL / 4; f2h_kernel<<<(n+255)/256, blk>>>(
                                    wv, hw + (size_t)(QDIM + KVDIM) * DMODEL, n);
        n = DMODEL * QDIM / 4;  f2h_kernel<<<(n+255)/256, blk>>>(wo, hwo, n);
    }

    // Fused QKV projection: [2048 x 4608] fp32 out
    gemm_h<<<dim3(QKVN / 128, NTOK / 128), blk, HGEMM_SMEM>>>(
        hx, hw, fqkv, NTOK, QKVN, DMODEL);

    // RMSNorm + RoPE -> fp16 (q scaled by 1/sqrt(96))
    {
        const float scale = 0.1020620726159658f;
        int rows_q = NTOK * NHEADS;
        int rows_k = NTOK * NKV;
        norm_rope_h_kernel<<<(rows_q * 32 + 255) / 256, blk>>>(
            fqkv, hqk, qnw, cosb, sinb, NHEADS, rows_q, QKVN, QKH, scale);
        norm_rope_h_kernel<<<(rows_k * 32 + 255) / 256, blk>>>(
            fqkv + QDIM, hqk + QDIM, knw, cosb, sinb, NKV, rows_k, QKVN, QKH, 1.0f);
    }

    // V transpose + fp16
    v_transpose_kernel<<<dim3(BB * NKV, TT / 64, HD / 32), blk>>>(fqkv, hvT);

    // Attention (fp16 HMMA)
    attn_h_kernel<<<dim3(TT / 128, NHEADS, BB), blk, ATTN_SMEM_B>>>(hqk, hvT, ha);

    // Output projection
    gemm_h<<<dim3(QDIM / 128, NTOK / 128), blk, HGEMM_SMEM>>>(
        ha, hwo, out, NTOK, QDIM, DMODEL);
}